// round 1
// baseline (speedup 1.0000x reference)
#include <cuda_runtime.h>
#include <cstdint>

// Problem constants (GATAuto: B=8, N=2048, Fin=128, H=[128,128,64], C=128)
#define BB 8
#define NN 2048
#define RTOT (BB*NN)          // 16384 rows

// ---------------- scratch (device globals; no allocation allowed) ----------
__device__ float    g_h[RTOT*128];       // layer pre-activations h = in @ W
__device__ float    g_o[RTOT*128];       // layer outputs relu(att @ h)
__device__ float    g_es[RTOT], g_u[RTOT], g_p[RTOT];
__device__ float    g_ed[RTOT], g_v[RTOT], g_q[RTOT];
__device__ unsigned g_mask[NN*(NN/32)];  // adjacency bitmask, 512KB
__device__ float    g_part[256*1024];    // final-linear split-K partials

// ---------------- adjacency bitmask ----------------------------------------
__global__ void build_mask_kernel(const float* __restrict__ adj) {
    int w    = blockIdx.x * 8 + (threadIdx.x >> 5);  // word index, 131072 total
    int lane = threadIdx.x & 31;
    int row  = w >> 6;
    int wc   = w & 63;
    float av = adj[(size_t)row * NN + wc * 32 + lane];
    unsigned m = __ballot_sync(0xffffffffu, av > 0.0f);
    if (lane == 0) g_mask[w] = m;
}

// ---------------- h = X @ W  (R=16384 rows, K=128, Fout=FOUT) ---------------
// BM=64, BK=16, 256 threads, thread tile 4 x (FOUT/16)
template <int FOUT>
__global__ __launch_bounds__(256) void sgemm_h_kernel(
    const float* __restrict__ X, const float* __restrict__ W, float* __restrict__ H)
{
    constexpr int TN = FOUT / 16;
    __shared__ float sX[16][68];
    __shared__ float sW[16][FOUT + 4];

    const int tid  = threadIdx.x;
    const int row0 = blockIdx.x * 64;
    const int tr   = tid >> 4;   // 0..15 (4 rows each)
    const int tc   = tid & 15;   // 0..15 (TN cols each)

    float acc[4][TN];
#pragma unroll
    for (int r = 0; r < 4; r++)
#pragma unroll
        for (int c = 0; c < TN; c++) acc[r][c] = 0.0f;

    for (int f0 = 0; f0 < 128; f0 += 16) {
        __syncthreads();
        // X tile 64x16 -> transposed sX[k][row]
        {
            int k  = tid & 15;
            int rr = tid >> 4;
#pragma unroll
            for (int s = 0; s < 4; s++) {
                int r = rr + s * 16;
                sX[k][r] = X[(size_t)(row0 + r) * 128 + f0 + k];
            }
        }
        // W tile 16 x FOUT
        for (int idx = tid; idx < 16 * FOUT; idx += 256) {
            int kk = idx / FOUT, o = idx % FOUT;
            sW[kk][o] = W[(size_t)(f0 + kk) * FOUT + o];
        }
        __syncthreads();
#pragma unroll
        for (int k = 0; k < 16; k++) {
            float ra[4], rb[TN];
            *(float4*)ra = *(const float4*)&sX[k][tr * 4];
            if (TN == 8) {
                *(float4*)&rb[0] = *(const float4*)&sW[k][tc * 8];
                *(float4*)&rb[4] = *(const float4*)&sW[k][tc * 8 + 4];
            } else {
                *(float4*)&rb[0] = *(const float4*)&sW[k][tc * 4];
            }
#pragma unroll
            for (int r = 0; r < 4; r++)
#pragma unroll
                for (int c = 0; c < TN; c++) acc[r][c] += ra[r] * rb[c];
        }
    }
    // store (vectorized)
#pragma unroll
    for (int r = 0; r < 4; r++) {
        size_t base = (size_t)(row0 + tr * 4 + r) * FOUT + tc * TN;
        float4 v0 = make_float4(acc[r][0], acc[r][1], acc[r][2], acc[r][3]);
        *(float4*)&H[base] = v0;
        if (TN == 8) {
            float4 v1 = make_float4(acc[r][4], acc[r][5], acc[r][6], acc[r][7]);
            *(float4*)&H[base + 4] = v1;
        }
    }
}

// ---------------- per-row attention stats: es, ed and exp factors ----------
template <int FOUT>
__global__ __launch_bounds__(256) void stats_kernel(
    const float* __restrict__ H, const float* __restrict__ as, const float* __restrict__ ad)
{
    int warp = threadIdx.x >> 5, lane = threadIdx.x & 31;
    int row  = blockIdx.x * 8 + warp;   // [0, 16384)
    const float* hr = H + (size_t)row * FOUT;
    float s1 = 0.0f, s2 = 0.0f;
#pragma unroll
    for (int o = lane; o < FOUT; o += 32) {
        float hv = hr[o];
        s1 += hv * as[o];
        s2 += hv * ad[o];
    }
#pragma unroll
    for (int off = 16; off; off >>= 1) {
        s1 += __shfl_xor_sync(0xffffffffu, s1, off);
        s2 += __shfl_xor_sync(0xffffffffu, s2, off);
    }
    if (lane == 0) {
        g_es[row] = s1; g_u[row] = __expf(s1); g_p[row] = __expf(0.2f * s1);
        g_ed[row] = s2; g_v[row] = __expf(s2); g_q[row] = __expf(0.2f * s2);
    }
}

// ---------------- fused masked-attention GEMM -------------------------------
// out[b,i,:] = relu( (sum_j P_ij h[b,j,:]) / (sum_j P_ij) )
// P_ij = mask_ij ? ( (es_i+ed_j>=0) ? u_i*v_j : p_i*q_j ) : 0
// BM=128, BN=FOUT, BK=32, 256 threads, thread tile 8 x (FOUT/16)
template <int FOUT>
__global__ __launch_bounds__(256) void attn_kernel(
    const float* __restrict__ H, float* __restrict__ O)
{
    constexpr int TN = FOUT / 16;
    const int b   = blockIdx.y;
    const int it  = blockIdx.x;
    const int tid = threadIdx.x;

    __shared__ float    sA[32][132];
    __shared__ float    sB[32][FOUT + 4];
    __shared__ float    ses[128], su[128], sp[128], ssum[128];
    __shared__ float    sed[32], sv[32], sq[32];
    __shared__ unsigned smask[128];

    const int i0   = it * 128;
    const int base = b * NN;

    if (tid < 128) {
        int i = i0 + tid;
        ses[tid] = g_es[base + i];
        su[tid]  = g_u[base + i];
        sp[tid]  = g_p[base + i];
    }

    float acc[8][TN];
#pragma unroll
    for (int r = 0; r < 8; r++)
#pragma unroll
        for (int c = 0; c < TN; c++) acc[r][c] = 0.0f;
    float rsum = 0.0f;

    const int tr = tid >> 4, tc = tid & 15;
    const int kA = tid & 31, iA = (tid >> 5) * 16;

    for (int jt = 0; jt < NN / 32; jt++) {
        __syncthreads();
        int j0 = jt * 32;
        if (tid < 32) {
            sed[tid] = g_ed[base + j0 + tid];
            sv[tid]  = g_v[base + j0 + tid];
            sq[tid]  = g_q[base + j0 + tid];
        } else if (tid >= 64 && tid < 192) {
            int i = tid - 64;
            smask[i] = g_mask[(size_t)(i0 + i) * (NN / 32) + jt];
        }
        // H tile 32 x FOUT (float4 coalesced)
        {
            const float4* src = reinterpret_cast<const float4*>(H + (size_t)(base + j0) * FOUT);
            constexpr int V = 32 * FOUT / 4;
#pragma unroll 2
            for (int idx = tid; idx < V; idx += 256) {
                int k  = idx / (FOUT / 4);
                int o4 = idx % (FOUT / 4);
                *(float4*)&sB[k][o4 * 4] = src[idx];
            }
        }
        __syncthreads();
        // build A tile: thread handles fixed k, 16 rows
        {
            float edj = sed[kA], vj = sv[kA], qj = sq[kA];
#pragma unroll
            for (int ii = 0; ii < 16; ii++) {
                int i = iA + ii;
                float a = 0.0f;
                if ((smask[i] >> kA) & 1u) {
                    float t = ses[i] + edj;
                    a = (t >= 0.0f) ? su[i] * vj : sp[i] * qj;
                }
                sA[kA][i] = a;
            }
        }
        __syncthreads();
        // GEMM over this tile
#pragma unroll
        for (int k = 0; k < 32; k++) {
            float ra[8], rb[TN];
            *(float4*)&ra[0] = *(const float4*)&sA[k][tr * 8];
            *(float4*)&ra[4] = *(const float4*)&sA[k][tr * 8 + 4];
            if (TN == 8) {
                *(float4*)&rb[0] = *(const float4*)&sB[k][tc * 8];
                *(float4*)&rb[4] = *(const float4*)&sB[k][tc * 8 + 4];
            } else {
                *(float4*)&rb[0] = *(const float4*)&sB[k][tc * 4];
            }
#pragma unroll
            for (int r = 0; r < 8; r++)
#pragma unroll
                for (int c = 0; c < TN; c++) acc[r][c] += ra[r] * rb[c];
        }
        // softmax denominator: row sums of A
        if (tid < 128) {
#pragma unroll
            for (int k = 0; k < 32; k++) rsum += sA[k][tid];
        }
    }
    if (tid < 128) ssum[tid] = rsum;
    __syncthreads();

#pragma unroll
    for (int r = 0; r < 8; r++) {
        float inv = 1.0f / ssum[tr * 8 + r];
        size_t rowbase = (size_t)(base + i0 + tr * 8 + r) * FOUT + tc * TN;
        float o0 = acc[r][0] * inv, o1 = acc[r][1] * inv, o2 = acc[r][2] * inv, o3 = acc[r][3] * inv;
        float4 v0 = make_float4(fmaxf(o0, 0.f), fmaxf(o1, 0.f), fmaxf(o2, 0.f), fmaxf(o3, 0.f));
        *(float4*)&O[rowbase] = v0;
        if (TN == 8) {
            float o4 = acc[r][4] * inv, o5 = acc[r][5] * inv, o6 = acc[r][6] * inv, o7 = acc[r][7] * inv;
            float4 v1 = make_float4(fmaxf(o4, 0.f), fmaxf(o5, 0.f), fmaxf(o6, 0.f), fmaxf(o7, 0.f));
            *(float4*)&O[rowbase + 4] = v1;
        }
    }
}

// ---------------- final linear: y[8,128] = X[8,131072] @ Wlin + blin --------
__global__ __launch_bounds__(128) void final_partial_kernel(
    const float* __restrict__ X, const float* __restrict__ Wlin)
{
    int c  = threadIdx.x;            // column 0..127
    int s  = blockIdx.x;             // split 0..255
    int k0 = s * 512;
    float acc[8] = {0, 0, 0, 0, 0, 0, 0, 0};
    for (int k = k0; k < k0 + 512; k++) {
        float w = Wlin[(size_t)k * 128 + c];
#pragma unroll
        for (int b = 0; b < 8; b++) acc[b] += X[(size_t)b * 131072 + k] * w;
    }
#pragma unroll
    for (int b = 0; b < 8; b++) g_part[s * 1024 + b * 128 + c] = acc[b];
}

__global__ __launch_bounds__(256) void final_reduce_kernel(
    const float* __restrict__ blin, float* __restrict__ out)
{
    int idx = blockIdx.x * 256 + threadIdx.x;   // 0..1023
    if (idx < 1024) {
        float s = 0.0f;
        for (int sp = 0; sp < 256; sp++) s += g_part[sp * 1024 + idx];
        out[idx] = s + blin[idx & 127];
    }
}

// ---------------- host driver ------------------------------------------------
extern "C" void kernel_launch(void* const* d_in, const int* in_sizes, int n_in,
                              void* d_out, int out_size)
{
    const float* x    = (const float*)d_in[0];
    const float* adj  = (const float*)d_in[1];
    const float* W1   = (const float*)d_in[2];
    const float* a1s  = (const float*)d_in[3];
    const float* a1d  = (const float*)d_in[4];
    const float* W2   = (const float*)d_in[5];
    const float* a2s  = (const float*)d_in[6];
    const float* a2d  = (const float*)d_in[7];
    const float* W3   = (const float*)d_in[8];
    const float* a3s  = (const float*)d_in[9];
    const float* a3d  = (const float*)d_in[10];
    const float* Wlin = (const float*)d_in[11];
    const float* blin = (const float*)d_in[12];

    void* ph; cudaGetSymbolAddress(&ph, g_h);
    void* po; cudaGetSymbolAddress(&po, g_o);
    float* hbuf = (float*)ph;
    float* obuf = (float*)po;

    // adjacency bitmask (once per launch; deterministic)
    build_mask_kernel<<<16384, 256>>>(adj);

    // layer 1 (Fin=128 -> 128)
    sgemm_h_kernel<128><<<256, 256>>>(x, W1, hbuf);
    stats_kernel<128><<<2048, 256>>>(hbuf, a1s, a1d);
    attn_kernel<128><<<dim3(16, 8), 256>>>(hbuf, obuf);

    // layer 2 (128 -> 128)
    sgemm_h_kernel<128><<<256, 256>>>(obuf, W2, hbuf);
    stats_kernel<128><<<2048, 256>>>(hbuf, a2s, a2d);
    attn_kernel<128><<<dim3(16, 8), 256>>>(hbuf, obuf);

    // layer 3 (128 -> 64)
    sgemm_h_kernel<64><<<256, 256>>>(obuf, W3, hbuf);
    stats_kernel<64><<<2048, 256>>>(hbuf, a3s, a3d);
    attn_kernel<64><<<dim3(16, 8), 256>>>(hbuf, obuf);

    // final linear
    final_partial_kernel<<<256, 128>>>(obuf, Wlin);
    final_reduce_kernel<<<4, 256>>>(blin, (float*)d_out);
}

// round 3
// speedup vs baseline: 1.5607x; 1.5607x over previous
#include <cuda_runtime.h>
#include <cuda_bf16.h>
#include <cstdint>

// Problem constants (GATAuto: B=8, N=2048, Fin=128, H=[128,128,64], C=128)
#define BB 8
#define NN 2048
#define RTOT (BB*NN)          // 16384 rows

// ---------------- scratch (device globals; no allocation allowed) ----------
__device__ __align__(16) __nv_bfloat16 g_bhi[128 * RTOT];  // h transposed, bf16 hi  [o][row]
__device__ __align__(16) __nv_bfloat16 g_blo[128 * RTOT];  // h transposed, bf16 lo  [o][row]
__device__ __align__(16) float    g_o[RTOT * 128];         // layer outputs (row-major)
__device__ float    g_es[RTOT], g_u[RTOT], g_p[RTOT];
__device__ float    g_ed[RTOT], g_v[RTOT], g_q[RTOT];
__device__ unsigned g_mask[NN * (NN / 32)];                // adjacency bitmask, 512KB
__device__ float    g_part[256 * 1024];                    // final-linear split-K partials

// ======================= warp MMA helpers (baseline PTX) =====================
__device__ __forceinline__ uint32_t smem_to_u32(const void* p) {
    uint32_t a;
    asm("{ .reg .u64 t; cvta.to.shared.u64 t, %1; cvt.u32.u64 %0, t; }" : "=r"(a) : "l"(p));
    return a;
}
__device__ __forceinline__ void ldmx4(uint32_t& r0, uint32_t& r1, uint32_t& r2, uint32_t& r3,
                                      uint32_t addr) {
    asm volatile("ldmatrix.sync.aligned.m8n8.x4.shared.b16 {%0,%1,%2,%3}, [%4];"
                 : "=r"(r0), "=r"(r1), "=r"(r2), "=r"(r3) : "r"(addr));
}
__device__ __forceinline__ void mma_bf16(float* d, uint32_t a0, uint32_t a1, uint32_t a2,
                                         uint32_t a3, uint32_t b0, uint32_t b1) {
    asm volatile("mma.sync.aligned.m16n8k16.row.col.f32.bf16.bf16.f32 "
                 "{%0,%1,%2,%3}, {%4,%5,%6,%7}, {%8,%9}, {%0,%1,%2,%3};"
                 : "+f"(d[0]), "+f"(d[1]), "+f"(d[2]), "+f"(d[3])
                 : "r"(a0), "r"(a1), "r"(a2), "r"(a3), "r"(b0), "r"(b1));
}

// ---------------- adjacency bitmask ----------------------------------------
__global__ void build_mask_kernel(const float* __restrict__ adj) {
    int w    = blockIdx.x * 8 + (threadIdx.x >> 5);
    int lane = threadIdx.x & 31;
    int row  = w >> 6;
    int wc   = w & 63;
    float av = adj[(size_t)row * NN + wc * 32 + lane];
    unsigned m = __ballot_sync(0xffffffffu, av > 0.0f);
    if (lane == 0) g_mask[w] = m;
}

// ---------------- h = X @ W, transposed bf16 hi/lo out + fused stats --------
// Also computes es/ed (fp32) and their exp factors per row.
template <int FOUT>
__global__ __launch_bounds__(256) void sgemm_h_kernel(
    const float* __restrict__ X, const float* __restrict__ W,
    const float* __restrict__ as, const float* __restrict__ ad,
    __nv_bfloat16* __restrict__ Hhi, __nv_bfloat16* __restrict__ Hlo)
{
    constexpr int TN = FOUT / 16;
    __shared__ float sX[16][68];
    __shared__ float sW[16][FOUT + 4];
    __shared__ float sRed1[64][17];
    __shared__ float sRed2[64][17];

    const int tid  = threadIdx.x;
    const int row0 = blockIdx.x * 64;
    const int tr   = tid >> 4;
    const int tc   = tid & 15;

    float acc[4][TN];
#pragma unroll
    for (int r = 0; r < 4; r++)
#pragma unroll
        for (int c = 0; c < TN; c++) acc[r][c] = 0.0f;

    for (int f0 = 0; f0 < 128; f0 += 16) {
        __syncthreads();
        {
            int k  = tid & 15;
            int rr = tid >> 4;
#pragma unroll
            for (int s = 0; s < 4; s++) {
                int r = rr + s * 16;
                sX[k][r] = X[(size_t)(row0 + r) * 128 + f0 + k];
            }
        }
        for (int idx = tid; idx < 16 * FOUT; idx += 256) {
            int kk = idx / FOUT, o = idx % FOUT;
            sW[kk][o] = W[(size_t)(f0 + kk) * FOUT + o];
        }
        __syncthreads();
#pragma unroll
        for (int k = 0; k < 16; k++) {
            float ra[4], rb[TN];
            *(float4*)ra = *(const float4*)&sX[k][tr * 4];
            if (TN == 8) {
                *(float4*)&rb[0] = *(const float4*)&sW[k][tc * 8];
                *(float4*)&rb[4] = *(const float4*)&sW[k][tc * 8 + 4];
            } else {
                *(float4*)&rb[0] = *(const float4*)&sW[k][tc * 4];
            }
#pragma unroll
            for (int r = 0; r < 4; r++)
#pragma unroll
                for (int c = 0; c < TN; c++) acc[r][c] += ra[r] * rb[c];
        }
    }

    // ---- fused stats partials: s1 = h.as, s2 = h.ad over this thread's cols
    float s1[4] = {0, 0, 0, 0}, s2[4] = {0, 0, 0, 0};
#pragma unroll
    for (int c = 0; c < TN; c++) {
        float av = __ldg(as + tc * TN + c);
        float dv = __ldg(ad + tc * TN + c);
#pragma unroll
        for (int r = 0; r < 4; r++) {
            s1[r] += acc[r][c] * av;
            s2[r] += acc[r][c] * dv;
        }
    }
    __syncthreads();
#pragma unroll
    for (int r = 0; r < 4; r++) {
        sRed1[tr * 4 + r][tc] = s1[r];
        sRed2[tr * 4 + r][tc] = s2[r];
    }

    // ---- transposed bf16 hi/lo store
#pragma unroll
    for (int c = 0; c < TN; c++) {
        int col = tc * TN + c;
        float v0 = acc[0][c], v1 = acc[1][c], v2 = acc[2][c], v3 = acc[3][c];
        __nv_bfloat16 b0 = __float2bfloat16(v0), b1 = __float2bfloat16(v1);
        __nv_bfloat16 b2 = __float2bfloat16(v2), b3 = __float2bfloat16(v3);
        __nv_bfloat162 h01, h23, l01, l23;
        h01.x = b0; h01.y = b1; h23.x = b2; h23.y = b3;
        l01.x = __float2bfloat16(v0 - __bfloat162float(b0));
        l01.y = __float2bfloat16(v1 - __bfloat162float(b1));
        l23.x = __float2bfloat16(v2 - __bfloat162float(b2));
        l23.y = __float2bfloat16(v3 - __bfloat162float(b3));
        size_t off = (size_t)col * RTOT + row0 + tr * 4;
        *(__nv_bfloat162*)(Hhi + off)     = h01;
        *(__nv_bfloat162*)(Hhi + off + 2) = h23;
        *(__nv_bfloat162*)(Hlo + off)     = l01;
        *(__nv_bfloat162*)(Hlo + off + 2) = l23;
    }

    __syncthreads();
    if (tid < 64) {
        float t1 = 0.0f, t2 = 0.0f;
#pragma unroll
        for (int t = 0; t < 16; t++) { t1 += sRed1[tid][t]; t2 += sRed2[tid][t]; }
        int gr = row0 + tid;
        g_es[gr] = t1; g_u[gr] = __expf(t1); g_p[gr] = __expf(0.2f * t1);
        g_ed[gr] = t2; g_v[gr] = __expf(t2); g_q[gr] = __expf(0.2f * t2);
    }
}

// ---------------- fused masked-attention via mma.sync bf16 split ------------
// out[b,i,:] = relu( (sum_j P_ij h[b,j,:]) / (sum_j P_ij) )
// P_ij = mask_ij ? ( (es_i+ed_j>=0) ? u_i*v_j : p_i*q_j ) : 0
// D(fp32) = Phi@Hhi + Phi@Hlo + Plo@Hhi  (lo*lo dropped)
template <int FOUT>
__global__ __launch_bounds__(256) void attn_mma_kernel(
    const __nv_bfloat16* __restrict__ Bhi, const __nv_bfloat16* __restrict__ Blo,
    float* __restrict__ O)
{
    constexpr int ROWB = 144;                      // 72 bf16 padded stride (bytes)
    constexpr uint32_t OFF_ES  = 0;                // 128 f32
    constexpr uint32_t OFF_U   = 512;
    constexpr uint32_t OFF_P   = 1024;
    constexpr uint32_t OFF_ED  = 1536;             // 64 f32
    constexpr uint32_t OFF_V   = 1792;
    constexpr uint32_t OFF_Q   = 2048;
    constexpr uint32_t OFF_SUM = 2304;             // 128 f32
    constexpr uint32_t OFF_PHI = 3072;             // 128 x 72 bf16
    constexpr uint32_t OFF_PLO = OFF_PHI + 128 * ROWB;
    constexpr uint32_t OFF_BHI = OFF_PLO + 128 * ROWB;   // FOUT x 72 bf16 (N x K = B^T)
    constexpr uint32_t OFF_BLO = OFF_BHI + FOUT * ROWB;

    extern __shared__ char smem[];
    const uint32_t sb = smem_to_u32(smem);
    const int tid  = threadIdx.x;
    const int wid  = tid >> 5;
    const int lane = tid & 31;

    const int b    = blockIdx.y;
    const int i0   = blockIdx.x * 128;
    const int base = b * NN;

    float* ses  = (float*)(smem + OFF_ES);
    float* su   = (float*)(smem + OFF_U);
    float* sp   = (float*)(smem + OFF_P);
    float* sed  = (float*)(smem + OFF_ED);
    float* sv   = (float*)(smem + OFF_V);
    float* sq   = (float*)(smem + OFF_Q);
    float* ssum = (float*)(smem + OFF_SUM);

    if (tid < 128) {
        int i = base + i0 + tid;
        ses[tid] = g_es[i]; su[tid] = g_u[i]; sp[tid] = g_p[i];
    }

    constexpr int NT = FOUT / 8;     // 8-col n tiles
    float acc[NT][4];
#pragma unroll
    for (int n = 0; n < NT; n++)
#pragma unroll
        for (int q = 0; q < 4; q++) acc[n][q] = 0.0f;
    float rsum = 0.0f;

    // per-thread P-build coordinates
    const int iP = tid >> 1;
    const int jh = tid & 1;

    // ldmatrix source addresses (fixed per thread)
    const int arow  = wid * 16 + (lane & 7) + (((lane >> 3) & 1) << 3);
    const int akoff = (lane >> 4) << 4;
    const uint32_t aHiBase = sb + OFF_PHI + arow * ROWB + akoff;
    const uint32_t aLoBase = sb + OFF_PLO + arow * ROWB + akoff;
    const int brow  = (lane & 7) + ((lane >> 4) << 3);
    const int bkoff = ((lane >> 3) & 1) << 4;
    const uint32_t bHiBase = sb + OFF_BHI + brow * ROWB + bkoff;
    const uint32_t bLoBase = sb + OFF_BLO + brow * ROWB + bkoff;

    __syncthreads();   // ses/su/sp visible (and before first tile writes)
    const float esi = ses[iP], ui = su[iP], pi = sp[iP];

    for (int jt = 0; jt < NN / 64; jt++) {
        const int j0 = jt * 64;
        // stage per-j stats
        if (tid < 64) {
            int j = base + j0 + tid;
            sed[tid] = g_ed[j]; sv[tid] = g_v[j]; sq[tid] = g_q[j];
        }
        // copy H tiles: g layout [o][row] -> smem N x K rows of 64 bf16 (128B)
        {
            constexpr int TOT = FOUT * 8;   // uint4 chunks per tile
#pragma unroll
            for (int t = 0; t < TOT / 256; t++) {
                int idx = tid + t * 256;
                int o = idx >> 3, c = idx & 7;
                size_t goff = (size_t)o * RTOT + base + j0;
                uint4 vh = ((const uint4*)(Bhi + goff))[c];
                uint4 vl = ((const uint4*)(Blo + goff))[c];
                uint32_t soff = (uint32_t)(o * ROWB + c * 16);
                *(uint4*)(smem + OFF_BHI + soff) = vh;
                *(uint4*)(smem + OFF_BLO + soff) = vl;
            }
        }
        __syncthreads();   // sed/sv/sq visible for P build

        // build P tile 128 x 64 (fp32 -> bf16 hi/lo) + row sums
        {
            unsigned mw = g_mask[(size_t)(i0 + iP) * (NN / 32) + jt * 2 + jh];
            char* dsthi = smem + OFF_PHI + iP * ROWB + jh * 64;
            char* dstlo = smem + OFF_PLO + iP * ROWB + jh * 64;
#pragma unroll
            for (int jj = 0; jj < 32; jj += 2) {
                int j = (jh << 5) + jj;
                float t0 = esi + sed[j];
                float t1 = esi + sed[j + 1];
                float v0 = ((mw >> jj) & 1u) ? ((t0 >= 0.0f) ? ui * sv[j] : pi * sq[j]) : 0.0f;
                float v1 = ((mw >> (jj + 1)) & 1u) ? ((t1 >= 0.0f) ? ui * sv[j + 1] : pi * sq[j + 1]) : 0.0f;
                rsum += v0 + v1;
                __nv_bfloat16 h0 = __float2bfloat16(v0), h1 = __float2bfloat16(v1);
                __nv_bfloat162 hh; hh.x = h0; hh.y = h1;
                __nv_bfloat162 ll;
                ll.x = __float2bfloat16(v0 - __bfloat162float(h0));
                ll.y = __float2bfloat16(v1 - __bfloat162float(h1));
                *(__nv_bfloat162*)(dsthi + jj * 2) = hh;
                *(__nv_bfloat162*)(dstlo + jj * 2) = ll;
            }
        }
        __syncthreads();   // tiles complete

        // warp MMA: 4 k-steps of 16
#pragma unroll
        for (int kk = 0; kk < 4; kk++) {
            uint32_t ah0, ah1, ah2, ah3, al0, al1, al2, al3;
            ldmx4(ah0, ah1, ah2, ah3, aHiBase + kk * 32);
            ldmx4(al0, al1, al2, al3, aLoBase + kk * 32);
#pragma unroll
            for (int np = 0; np < NT / 2; np++) {
                uint32_t bh0, bh1, bh2, bh3, bl0, bl1, bl2, bl3;
                ldmx4(bh0, bh1, bh2, bh3, bHiBase + np * 16 * ROWB + kk * 32);
                ldmx4(bl0, bl1, bl2, bl3, bLoBase + np * 16 * ROWB + kk * 32);
                mma_bf16(acc[np * 2],     ah0, ah1, ah2, ah3, bh0, bh1);
                mma_bf16(acc[np * 2],     ah0, ah1, ah2, ah3, bl0, bl1);
                mma_bf16(acc[np * 2],     al0, al1, al2, al3, bh0, bh1);
                mma_bf16(acc[np * 2 + 1], ah0, ah1, ah2, ah3, bh2, bh3);
                mma_bf16(acc[np * 2 + 1], ah0, ah1, ah2, ah3, bl2, bl3);
                mma_bf16(acc[np * 2 + 1], al0, al1, al2, al3, bh2, bh3);
            }
        }
        __syncthreads();   // done reading tiles before next overwrite
    }

    // softmax denominators
    {
        float tot = rsum + __shfl_xor_sync(0xffffffffu, rsum, 1);
        if (jh == 0) ssum[iP] = tot;
    }
    __syncthreads();

    // epilogue: D / rowsum, relu, store fp32 row-major
    {
        int r0 = wid * 16 + (lane >> 2);
        int r1 = r0 + 8;
        float inv0 = 1.0f / ssum[r0];
        float inv1 = 1.0f / ssum[r1];
        float* o0 = O + (size_t)(base + i0 + r0) * FOUT + (lane & 3) * 2;
        float* o1 = O + (size_t)(base + i0 + r1) * FOUT + (lane & 3) * 2;
#pragma unroll
        for (int n = 0; n < NT; n++) {
            float2 w0, w1;
            w0.x = fmaxf(acc[n][0] * inv0, 0.0f);
            w0.y = fmaxf(acc[n][1] * inv0, 0.0f);
            w1.x = fmaxf(acc[n][2] * inv1, 0.0f);
            w1.y = fmaxf(acc[n][3] * inv1, 0.0f);
            *(float2*)(o0 + n * 8) = w0;
            *(float2*)(o1 + n * 8) = w1;
        }
    }
}

// ---------------- final linear: y[8,128] = X[8,131072] @ Wlin + blin --------
__global__ __launch_bounds__(128) void final_partial_kernel(
    const float* __restrict__ X, const float* __restrict__ Wlin)
{
    int c  = threadIdx.x;
    int s  = blockIdx.x;
    int k0 = s * 512;
    float acc[8] = {0, 0, 0, 0, 0, 0, 0, 0};
    for (int k = k0; k < k0 + 512; k++) {
        float w = Wlin[(size_t)k * 128 + c];
#pragma unroll
        for (int b = 0; b < 8; b++) acc[b] += X[(size_t)b * 131072 + k] * w;
    }
#pragma unroll
    for (int b = 0; b < 8; b++) g_part[s * 1024 + b * 128 + c] = acc[b];
}

__global__ __launch_bounds__(256) void final_reduce_kernel(
    const float* __restrict__ blin, float* __restrict__ out)
{
    int idx = blockIdx.x * 256 + threadIdx.x;
    if (idx < 1024) {
        float s = 0.0f;
        for (int sp = 0; sp < 256; sp++) s += g_part[sp * 1024 + idx];
        out[idx] = s + blin[idx & 127];
    }
}

// ---------------- host driver ------------------------------------------------
extern "C" void kernel_launch(void* const* d_in, const int* in_sizes, int n_in,
                              void* d_out, int out_size)
{
    const float* x    = (const float*)d_in[0];
    const float* adj  = (const float*)d_in[1];
    const float* W1   = (const float*)d_in[2];
    const float* a1s  = (const float*)d_in[3];
    const float* a1d  = (const float*)d_in[4];
    const float* W2   = (const float*)d_in[5];
    const float* a2s  = (const float*)d_in[6];
    const float* a2d  = (const float*)d_in[7];
    const float* W3   = (const float*)d_in[8];
    const float* a3s  = (const float*)d_in[9];
    const float* a3d  = (const float*)d_in[10];
    const float* Wlin = (const float*)d_in[11];
    const float* blin = (const float*)d_in[12];

    void* pbh; cudaGetSymbolAddress(&pbh, g_bhi);
    void* pbl; cudaGetSymbolAddress(&pbl, g_blo);
    void* po;  cudaGetSymbolAddress(&po,  g_o);
    __nv_bfloat16* bhi = (__nv_bfloat16*)pbh;
    __nv_bfloat16* blo = (__nv_bfloat16*)pbl;
    float* obuf = (float*)po;

    constexpr int SM128 = 3072 + 2 * 128 * 144 + 2 * 128 * 144;  // 76800
    constexpr int SM64  = 3072 + 2 * 128 * 144 + 2 * 64 * 144;   // 58368
    cudaFuncSetAttribute(attn_mma_kernel<128>, cudaFuncAttributeMaxDynamicSharedMemorySize, SM128);
    cudaFuncSetAttribute(attn_mma_kernel<64>,  cudaFuncAttributeMaxDynamicSharedMemorySize, SM64);

    build_mask_kernel<<<16384, 256>>>(adj);

    // layer 1 (128 -> 128)
    sgemm_h_kernel<128><<<256, 256>>>(x, W1, a1s, a1d, bhi, blo);
    attn_mma_kernel<128><<<dim3(16, 8), 256, SM128>>>(bhi, blo, obuf);

    // layer 2 (128 -> 128)
    sgemm_h_kernel<128><<<256, 256>>>(obuf, W2, a2s, a2d, bhi, blo);
    attn_mma_kernel<128><<<dim3(16, 8), 256, SM128>>>(bhi, blo, obuf);

    // layer 3 (128 -> 64)
    sgemm_h_kernel<64><<<256, 256>>>(obuf, W3, a3s, a3d, bhi, blo);
    attn_mma_kernel<64><<<dim3(16, 8), 256, SM64>>>(bhi, blo, obuf);

    // final linear
    final_partial_kernel<<<256, 128>>>(obuf, Wlin);
    final_reduce_kernel<<<4, 256>>>(blin, (float*)d_out);
}

// round 4
// speedup vs baseline: 2.0422x; 1.3085x over previous
#include <cuda_runtime.h>
#include <cuda_bf16.h>
#include <cstdint>

// Problem constants (GATAuto: B=8, N=2048, Fin=128, H=[128,128,64], C=128)
#define BB 8
#define NN 2048
#define RTOT (BB*NN)          // 16384 rows
#define ZSPLIT 4
#define JT_PER ((NN/64)/ZSPLIT)   // 8 j-tiles per block

// ---------------- scratch (device globals; no allocation allowed) ----------
__device__ __align__(16) __nv_bfloat16 g_bhi[128 * RTOT];  // h transposed, bf16 hi  [o][row]
__device__ __align__(16) __nv_bfloat16 g_blo[128 * RTOT];  // h transposed, bf16 lo  [o][row]
__device__ __align__(16) float    g_o[RTOT * 128];         // layer outputs (row-major)
__device__ __align__(16) float    g_pd[(size_t)ZSPLIT * RTOT * 128];  // partial D (33.5MB)
__device__ float    g_ps[ZSPLIT * RTOT];                   // partial row sums
__device__ float    g_es[RTOT], g_u[RTOT], g_p[RTOT];
__device__ float    g_ed[RTOT], g_v[RTOT], g_q[RTOT];
__device__ unsigned g_mask[NN * (NN / 32)];                // adjacency bitmask, 512KB
__device__ float    g_part[256 * 1024];                    // final-linear split-K partials

// ======================= warp MMA helpers (baseline PTX) =====================
__device__ __forceinline__ uint32_t smem_to_u32(const void* p) {
    uint32_t a;
    asm("{ .reg .u64 t; cvta.to.shared.u64 t, %1; cvt.u32.u64 %0, t; }" : "=r"(a) : "l"(p));
    return a;
}
__device__ __forceinline__ void ldmx4(uint32_t& r0, uint32_t& r1, uint32_t& r2, uint32_t& r3,
                                      uint32_t addr) {
    asm volatile("ldmatrix.sync.aligned.m8n8.x4.shared.b16 {%0,%1,%2,%3}, [%4];"
                 : "=r"(r0), "=r"(r1), "=r"(r2), "=r"(r3) : "r"(addr));
}
__device__ __forceinline__ void mma_bf16(float* d, uint32_t a0, uint32_t a1, uint32_t a2,
                                         uint32_t a3, uint32_t b0, uint32_t b1) {
    asm volatile("mma.sync.aligned.m16n8k16.row.col.f32.bf16.bf16.f32 "
                 "{%0,%1,%2,%3}, {%4,%5,%6,%7}, {%8,%9}, {%0,%1,%2,%3};"
                 : "+f"(d[0]), "+f"(d[1]), "+f"(d[2]), "+f"(d[3])
                 : "r"(a0), "r"(a1), "r"(a2), "r"(a3), "r"(b0), "r"(b1));
}
#define CP_ASYNC16(dst, src) \
    asm volatile("cp.async.ca.shared.global [%0], [%1], 16;" :: "r"(dst), "l"(src))
#define CP_COMMIT() asm volatile("cp.async.commit_group;" ::: "memory")
#define CP_WAIT0()  asm volatile("cp.async.wait_group 0;" ::: "memory")

__device__ __forceinline__ uint32_t pack_bf16x2(float lo, float hi) {
    uint32_t r;
    asm("cvt.rn.bf16x2.f32 %0, %1, %2;" : "=r"(r) : "f"(hi), "f"(lo));
    return r;
}

// ---------------- adjacency bitmask ----------------------------------------
__global__ void build_mask_kernel(const float* __restrict__ adj) {
    int w    = blockIdx.x * 8 + (threadIdx.x >> 5);
    int lane = threadIdx.x & 31;
    int row  = w >> 6;
    int wc   = w & 63;
    float av = adj[(size_t)row * NN + wc * 32 + lane];
    unsigned m = __ballot_sync(0xffffffffu, av > 0.0f);
    if (lane == 0) g_mask[w] = m;
}

// ---------------- h = X @ W, transposed bf16 hi/lo out + fused stats --------
template <int FOUT>
__global__ __launch_bounds__(256) void sgemm_h_kernel(
    const float* __restrict__ X, const float* __restrict__ W,
    const float* __restrict__ as, const float* __restrict__ ad,
    __nv_bfloat16* __restrict__ Hhi, __nv_bfloat16* __restrict__ Hlo)
{
    constexpr int TN = FOUT / 16;
    __shared__ float sX[16][68];
    __shared__ float sW[16][FOUT + 4];
    __shared__ float sRed1[64][17];
    __shared__ float sRed2[64][17];

    const int tid  = threadIdx.x;
    const int row0 = blockIdx.x * 64;
    const int tr   = tid >> 4;
    const int tc   = tid & 15;

    float acc[4][TN];
#pragma unroll
    for (int r = 0; r < 4; r++)
#pragma unroll
        for (int c = 0; c < TN; c++) acc[r][c] = 0.0f;

    for (int f0 = 0; f0 < 128; f0 += 16) {
        __syncthreads();
        {
            int k  = tid & 15;
            int rr = tid >> 4;
#pragma unroll
            for (int s = 0; s < 4; s++) {
                int r = rr + s * 16;
                sX[k][r] = X[(size_t)(row0 + r) * 128 + f0 + k];
            }
        }
        for (int idx = tid; idx < 16 * FOUT; idx += 256) {
            int kk = idx / FOUT, o = idx % FOUT;
            sW[kk][o] = W[(size_t)(f0 + kk) * FOUT + o];
        }
        __syncthreads();
#pragma unroll
        for (int k = 0; k < 16; k++) {
            float ra[4], rb[TN];
            *(float4*)ra = *(const float4*)&sX[k][tr * 4];
            if (TN == 8) {
                *(float4*)&rb[0] = *(const float4*)&sW[k][tc * 8];
                *(float4*)&rb[4] = *(const float4*)&sW[k][tc * 8 + 4];
            } else {
                *(float4*)&rb[0] = *(const float4*)&sW[k][tc * 4];
            }
#pragma unroll
            for (int r = 0; r < 4; r++)
#pragma unroll
                for (int c = 0; c < TN; c++) acc[r][c] += ra[r] * rb[c];
        }
    }

    float s1[4] = {0, 0, 0, 0}, s2[4] = {0, 0, 0, 0};
#pragma unroll
    for (int c = 0; c < TN; c++) {
        float av = __ldg(as + tc * TN + c);
        float dv = __ldg(ad + tc * TN + c);
#pragma unroll
        for (int r = 0; r < 4; r++) {
            s1[r] += acc[r][c] * av;
            s2[r] += acc[r][c] * dv;
        }
    }
    __syncthreads();
#pragma unroll
    for (int r = 0; r < 4; r++) {
        sRed1[tr * 4 + r][tc] = s1[r];
        sRed2[tr * 4 + r][tc] = s2[r];
    }

#pragma unroll
    for (int c = 0; c < TN; c++) {
        int col = tc * TN + c;
        float v0 = acc[0][c], v1 = acc[1][c], v2 = acc[2][c], v3 = acc[3][c];
        uint32_t h01 = pack_bf16x2(v0, v1);
        uint32_t h23 = pack_bf16x2(v2, v3);
        float f0 = __int_as_float(h01 << 16), f1 = __int_as_float(h01 & 0xffff0000u);
        float f2 = __int_as_float(h23 << 16), f3 = __int_as_float(h23 & 0xffff0000u);
        uint32_t l01 = pack_bf16x2(v0 - f0, v1 - f1);
        uint32_t l23 = pack_bf16x2(v2 - f2, v3 - f3);
        size_t off = (size_t)col * RTOT + row0 + tr * 4;
        *(uint32_t*)(Hhi + off)     = h01;
        *(uint32_t*)(Hhi + off + 2) = h23;
        *(uint32_t*)(Hlo + off)     = l01;
        *(uint32_t*)(Hlo + off + 2) = l23;
    }

    __syncthreads();
    if (tid < 64) {
        float t1 = 0.0f, t2 = 0.0f;
#pragma unroll
        for (int t = 0; t < 16; t++) { t1 += sRed1[tid][t]; t2 += sRed2[tid][t]; }
        int gr = row0 + tid;
        g_es[gr] = t1; g_u[gr] = __expf(t1); g_p[gr] = __expf(0.2f * t1);
        g_ed[gr] = t2; g_v[gr] = __expf(t2); g_q[gr] = __expf(0.2f * t2);
    }
}

// ---------------- fused masked-attention, split-j partials ------------------
// Partial D over j in [z*512, z*512+512); P via rank-1 exp factorization.
// D(fp32) = Phi@Hhi + Phi@Hlo + Plo@Hhi  (lo*lo dropped)
template <int FOUT>
__global__ __launch_bounds__(256) void attn_mma_kernel(
    const __nv_bfloat16* __restrict__ Bhi, const __nv_bfloat16* __restrict__ Blo)
{
    constexpr int ROWB = 144;                    // P row stride (bytes)
    constexpr uint32_t OFF_ES  = 0;              // 128 f32
    constexpr uint32_t OFF_U   = 512;
    constexpr uint32_t OFF_P   = 1024;
    constexpr uint32_t OFF_SED = 1536;           // 512 f32
    constexpr uint32_t OFF_SV  = OFF_SED + 2048;
    constexpr uint32_t OFF_SQ  = OFF_SV + 2048;
    constexpr uint32_t OFF_PHI = 7680;           // 128 x 72 bf16 (padded rows)
    constexpr uint32_t OFF_PLO = OFF_PHI + 128 * ROWB;
    constexpr uint32_t OFF_B   = OFF_PLO + 128 * ROWB;   // 44544
    constexpr uint32_t BUFSTRIDE = 2u * FOUT * 128;      // hi + lo per buffer

    extern __shared__ char smem[];
    const uint32_t sb = smem_to_u32(smem);
    const int tid  = threadIdx.x;
    const int wid  = tid >> 5;
    const int lane = tid & 31;

    const int b    = blockIdx.y;
    const int i0   = blockIdx.x * 128;
    const int z    = blockIdx.z;
    const int base = b * NN;
    const int jbase = base + z * (JT_PER * 64);

    float* ses = (float*)(smem + OFF_ES);
    float* su  = (float*)(smem + OFF_U);
    float* sp  = (float*)(smem + OFF_P);
    float* sed = (float*)(smem + OFF_SED);
    float* sv  = (float*)(smem + OFF_SV);
    float* sq  = (float*)(smem + OFF_SQ);

    // ---- prologue staging ----
    if (tid < 128) {
        int i = base + i0 + tid;
        ses[tid] = g_es[i]; su[tid] = g_u[i]; sp[tid] = g_p[i];
    }
#pragma unroll
    for (int t = 0; t < 2; t++) {
        int idx = tid + t * 256;
        sed[idx] = g_ed[jbase + idx];
        sv[idx]  = g_v[jbase + idx];
        sq[idx]  = g_q[jbase + idx];
    }

    // B tile loader: tile l -> buffer buf (cp.async, swizzled 128B rows)
    auto load_B = [&](int l, int buf) {
        const uint32_t dbase = sb + OFF_B + buf * BUFSTRIDE;
        const size_t gcol = (size_t)(jbase + l * 64);
        constexpr int CH = FOUT * 8;   // 16B chunks per (hi or lo) tile
#pragma unroll
        for (int t = 0; t < CH / 256; t++) {
            int idx = tid + t * 256;
            int o = idx >> 3, c = idx & 7;
            uint32_t sw = (uint32_t)((c ^ (o & 7)) << 4) + o * 128;
            const char* shi = (const char*)(Bhi + (size_t)o * RTOT + gcol) + c * 16;
            const char* slo = (const char*)(Blo + (size_t)o * RTOT + gcol) + c * 16;
            CP_ASYNC16(dbase + sw, shi);
            CP_ASYNC16(dbase + FOUT * 128 + sw, slo);
        }
    };

    load_B(0, 0);
    CP_COMMIT();

    // per-thread P-build coordinates
    const int iP = tid >> 1;
    const int jh = tid & 1;

    // mask words for all local j-tiles
    unsigned mw[JT_PER];
    {
        const unsigned* mrow = g_mask + (size_t)(i0 + iP) * (NN / 32) + z * (JT_PER * 2) + jh;
#pragma unroll
        for (int l = 0; l < JT_PER; l++) mw[l] = mrow[l * 2];
    }

    // ldmatrix fixed addresses
    const int arow  = wid * 16 + (lane & 7) + (((lane >> 3) & 1) << 3);
    const int akoff = (lane >> 4) << 4;
    const uint32_t aHiBase = sb + OFF_PHI + arow * ROWB + akoff;
    const uint32_t aLoBase = sb + OFF_PLO + arow * ROWB + akoff;
    const int brow = (lane & 7) + ((lane >> 4) << 3);
    const int bsel = (lane >> 3) & 1;

    constexpr int NT = FOUT / 8;
    float acc[NT][4];
#pragma unroll
    for (int n = 0; n < NT; n++)
#pragma unroll
        for (int q = 0; q < 4; q++) acc[n][q] = 0.0f;
    float rsum = 0.0f;

    __syncthreads();
    const float esi = ses[iP], ui = su[iP], pi = sp[iP];
    char* dsthi = smem + OFF_PHI + iP * ROWB + jh * 64;
    char* dstlo = smem + OFF_PLO + iP * ROWB + jh * 64;

    for (int l = 0; l < JT_PER; l++) {
        CP_WAIT0();
        __syncthreads();   // B buf[l&1] ready; prior MMA done everywhere

        if (l + 1 < JT_PER) { load_B(l + 1, (l + 1) & 1); CP_COMMIT(); }

        // build P rows (warp-local ownership)
        {
            unsigned m = mw[l];
            const float* sedl = sed + l * 64 + (jh << 5);
            const float* svl  = sv  + l * 64 + (jh << 5);
            const float* sql  = sq  + l * 64 + (jh << 5);
#pragma unroll
            for (int jj = 0; jj < 32; jj += 2) {
                float t0 = esi + sedl[jj];
                float t1 = esi + sedl[jj + 1];
                float v0 = ((m >> jj) & 1u) ? ((t0 >= 0.0f) ? ui * svl[jj] : pi * sql[jj]) : 0.0f;
                float v1 = ((m >> (jj + 1)) & 1u) ? ((t1 >= 0.0f) ? ui * svl[jj + 1] : pi * sql[jj + 1]) : 0.0f;
                rsum += v0 + v1;
                uint32_t hp = pack_bf16x2(v0, v1);
                float f0 = __int_as_float(hp << 16);
                float f1 = __int_as_float(hp & 0xffff0000u);
                uint32_t lp = pack_bf16x2(v0 - f0, v1 - f1);
                *(uint32_t*)(dsthi + jj * 2) = hp;
                *(uint32_t*)(dstlo + jj * 2) = lp;
            }
        }
        __syncwarp();

        // MMA over buffer l&1
        const uint32_t bB = sb + OFF_B + (l & 1) * BUFSTRIDE;
#pragma unroll
        for (int kk = 0; kk < 4; kk++) {
            uint32_t ah0, ah1, ah2, ah3, al0, al1, al2, al3;
            ldmx4(ah0, ah1, ah2, ah3, aHiBase + kk * 32);
            ldmx4(al0, al1, al2, al3, aLoBase + kk * 32);
            int cIdx = kk * 2 + bsel;
#pragma unroll
            for (int np = 0; np < NT / 2; np++) {
                int r = np * 16 + brow;
                uint32_t ba = bB + r * 128 + (uint32_t)((cIdx ^ (r & 7)) << 4);
                uint32_t bh0, bh1, bh2, bh3, bl0, bl1, bl2, bl3;
                ldmx4(bh0, bh1, bh2, bh3, ba);
                ldmx4(bl0, bl1, bl2, bl3, ba + FOUT * 128);
                mma_bf16(acc[np * 2],     ah0, ah1, ah2, ah3, bh0, bh1);
                mma_bf16(acc[np * 2],     ah0, ah1, ah2, ah3, bl0, bl1);
                mma_bf16(acc[np * 2],     al0, al1, al2, al3, bh0, bh1);
                mma_bf16(acc[np * 2 + 1], ah0, ah1, ah2, ah3, bh2, bh3);
                mma_bf16(acc[np * 2 + 1], ah0, ah1, ah2, ah3, bl2, bl3);
                mma_bf16(acc[np * 2 + 1], al0, al1, al2, al3, bh2, bh3);
            }
        }
    }

    // partial row sums
    {
        float tot = rsum + __shfl_xor_sync(0xffffffffu, rsum, 1);
        if (jh == 0) g_ps[z * RTOT + base + i0 + iP] = tot;
    }

    // partial D store (fp32, no div/relu)
    {
        int r0 = wid * 16 + (lane >> 2);
        int r1 = r0 + 8;
        float* p0 = g_pd + (size_t)z * RTOT * 128 + (size_t)(base + i0 + r0) * FOUT + (lane & 3) * 2;
        float* p1 = g_pd + (size_t)z * RTOT * 128 + (size_t)(base + i0 + r1) * FOUT + (lane & 3) * 2;
#pragma unroll
        for (int n = 0; n < NT; n++) {
            *(float2*)(p0 + n * 8) = make_float2(acc[n][0], acc[n][1]);
            *(float2*)(p1 + n * 8) = make_float2(acc[n][2], acc[n][3]);
        }
    }
}

// ---------------- combine partials: out = relu(sum_z D / sum_z s) ----------
template <int FOUT>
__global__ __launch_bounds__(256) void combine_kernel(float* __restrict__ O) {
    int idx = blockIdx.x * 256 + threadIdx.x;       // one float4 of one row
    int row = idx / (FOUT / 4);
    int c4  = idx % (FOUT / 4);
    float rs = 0.0f;
    float4 d = make_float4(0.f, 0.f, 0.f, 0.f);
#pragma unroll
    for (int zz = 0; zz < ZSPLIT; zz++) {
        rs += g_ps[zz * RTOT + row];
        float4 t = *(const float4*)(g_pd + (size_t)zz * RTOT * 128 + (size_t)row * FOUT + c4 * 4);
        d.x += t.x; d.y += t.y; d.z += t.z; d.w += t.w;
    }
    float inv = 1.0f / rs;
    float4 o;
    o.x = fmaxf(d.x * inv, 0.0f);
    o.y = fmaxf(d.y * inv, 0.0f);
    o.z = fmaxf(d.z * inv, 0.0f);
    o.w = fmaxf(d.w * inv, 0.0f);
    *(float4*)(O + (size_t)row * FOUT + c4 * 4) = o;
}

// ---------------- final linear: y[8,128] = X[8,131072] @ Wlin + blin --------
__global__ __launch_bounds__(128) void final_partial_kernel(
    const float* __restrict__ X, const float* __restrict__ Wlin)
{
    int c  = threadIdx.x;
    int s  = blockIdx.x;
    int k0 = s * 512;
    float acc[8] = {0, 0, 0, 0, 0, 0, 0, 0};
    for (int k = k0; k < k0 + 512; k++) {
        float w = Wlin[(size_t)k * 128 + c];
#pragma unroll
        for (int b = 0; b < 8; b++) acc[b] += X[(size_t)b * 131072 + k] * w;
    }
#pragma unroll
    for (int b = 0; b < 8; b++) g_part[s * 1024 + b * 128 + c] = acc[b];
}

__global__ __launch_bounds__(256) void final_reduce_kernel(
    const float* __restrict__ blin, float* __restrict__ out)
{
    int idx = blockIdx.x * 256 + threadIdx.x;
    if (idx < 1024) {
        float s = 0.0f;
        for (int sp = 0; sp < 256; sp++) s += g_part[sp * 1024 + idx];
        out[idx] = s + blin[idx & 127];
    }
}

// ---------------- host driver ------------------------------------------------
extern "C" void kernel_launch(void* const* d_in, const int* in_sizes, int n_in,
                              void* d_out, int out_size)
{
    const float* x    = (const float*)d_in[0];
    const float* adj  = (const float*)d_in[1];
    const float* W1   = (const float*)d_in[2];
    const float* a1s  = (const float*)d_in[3];
    const float* a1d  = (const float*)d_in[4];
    const float* W2   = (const float*)d_in[5];
    const float* a2s  = (const float*)d_in[6];
    const float* a2d  = (const float*)d_in[7];
    const float* W3   = (const float*)d_in[8];
    const float* a3s  = (const float*)d_in[9];
    const float* a3d  = (const float*)d_in[10];
    const float* Wlin = (const float*)d_in[11];
    const float* blin = (const float*)d_in[12];

    void* pbh; cudaGetSymbolAddress(&pbh, g_bhi);
    void* pbl; cudaGetSymbolAddress(&pbl, g_blo);
    void* po;  cudaGetSymbolAddress(&po,  g_o);
    __nv_bfloat16* bhi = (__nv_bfloat16*)pbh;
    __nv_bfloat16* blo = (__nv_bfloat16*)pbl;
    float* obuf = (float*)po;

    constexpr int SM128 = 44544 + 2 * 2 * 128 * 128;  // 110080
    constexpr int SM64  = 44544 + 2 * 2 * 64 * 128;   // 77312
    cudaFuncSetAttribute(attn_mma_kernel<128>, cudaFuncAttributeMaxDynamicSharedMemorySize, SM128);
    cudaFuncSetAttribute(attn_mma_kernel<64>,  cudaFuncAttributeMaxDynamicSharedMemorySize, SM64);

    build_mask_kernel<<<16384, 256>>>(adj);

    // layer 1 (128 -> 128)
    sgemm_h_kernel<128><<<256, 256>>>(x, W1, a1s, a1d, bhi, blo);
    attn_mma_kernel<128><<<dim3(16, 8, ZSPLIT), 256, SM128>>>(bhi, blo);
    combine_kernel<128><<<RTOT * 128 / 4 / 256, 256>>>(obuf);

    // layer 2 (128 -> 128)
    sgemm_h_kernel<128><<<256, 256>>>(obuf, W2, a2s, a2d, bhi, blo);
    attn_mma_kernel<128><<<dim3(16, 8, ZSPLIT), 256, SM128>>>(bhi, blo);
    combine_kernel<128><<<RTOT * 128 / 4 / 256, 256>>>(obuf);

    // layer 3 (128 -> 64)
    sgemm_h_kernel<64><<<256, 256>>>(obuf, W3, a3s, a3d, bhi, blo);
    attn_mma_kernel<64><<<dim3(16, 8, ZSPLIT), 256, SM64>>>(bhi, blo);
    combine_kernel<64><<<RTOT * 64 / 4 / 256, 256>>>(obuf);

    // final linear
    final_partial_kernel<<<256, 128>>>(obuf, Wlin);
    final_reduce_kernel<<<4, 256>>>(blin, (float*)d_out);
}

// round 5
// speedup vs baseline: 2.3219x; 1.1370x over previous
#include <cuda_runtime.h>
#include <cuda_fp16.h>
#include <cstdint>

// Problem constants (GATAuto: B=8, N=2048, Fin=128, H=[128,128,64], C=128)
#define BB 8
#define NN 2048
#define RTOT (BB*NN)          // 16384 rows
#define ZSPLIT 4
#define JT_PER ((NN/64)/ZSPLIT)   // 8 j-tiles per block

// ---------------- scratch (device globals; no allocation allowed) ----------
__device__ __align__(16) __half g_hh[128 * RTOT];          // h transposed fp16 [o][row]
__device__ __align__(16) float  g_o[RTOT * 128];           // layer outputs (row-major)
__device__ __align__(16) float  g_pd[(size_t)ZSPLIT * RTOT * 128];  // partial D
__device__ float    g_ps[ZSPLIT * RTOT];                   // partial row sums
__device__ float    g_es[RTOT], g_r[RTOT];                 // es, exp(-0.8 es)
__device__ float    g_ed[RTOT], g_v[RTOT], g_q[RTOT];      // ed, exp(ed), exp(0.2 ed)
__device__ unsigned g_mask[NN * (NN / 32)];                // adjacency bitmask, 512KB
__device__ float    g_part[256 * 1024];                    // final-linear split-K partials

// ======================= warp MMA helpers (baseline PTX) =====================
__device__ __forceinline__ uint32_t smem_to_u32(const void* p) {
    uint32_t a;
    asm("{ .reg .u64 t; cvta.to.shared.u64 t, %1; cvt.u32.u64 %0, t; }" : "=r"(a) : "l"(p));
    return a;
}
__device__ __forceinline__ void ldmx4(uint32_t& r0, uint32_t& r1, uint32_t& r2, uint32_t& r3,
                                      uint32_t addr) {
    asm volatile("ldmatrix.sync.aligned.m8n8.x4.shared.b16 {%0,%1,%2,%3}, [%4];"
                 : "=r"(r0), "=r"(r1), "=r"(r2), "=r"(r3) : "r"(addr));
}
__device__ __forceinline__ void mma_f16(float* d, uint32_t a0, uint32_t a1, uint32_t a2,
                                        uint32_t a3, uint32_t b0, uint32_t b1) {
    asm volatile("mma.sync.aligned.m16n8k16.row.col.f32.f16.f16.f32 "
                 "{%0,%1,%2,%3}, {%4,%5,%6,%7}, {%8,%9}, {%0,%1,%2,%3};"
                 : "+f"(d[0]), "+f"(d[1]), "+f"(d[2]), "+f"(d[3])
                 : "r"(a0), "r"(a1), "r"(a2), "r"(a3), "r"(b0), "r"(b1));
}
#define CP_ASYNC16(dst, src) \
    asm volatile("cp.async.ca.shared.global [%0], [%1], 16;" :: "r"(dst), "l"(src))
#define CP_COMMIT() asm volatile("cp.async.commit_group;" ::: "memory")
#define CP_WAIT0()  asm volatile("cp.async.wait_group 0;" ::: "memory")

// ---------------- adjacency bitmask ----------------------------------------
__global__ void build_mask_kernel(const float* __restrict__ adj) {
    int w    = blockIdx.x * 8 + (threadIdx.x >> 5);
    int lane = threadIdx.x & 31;
    int row  = w >> 6;
    int wc   = w & 63;
    float av = adj[(size_t)row * NN + wc * 32 + lane];
    unsigned m = __ballot_sync(0xffffffffu, av > 0.0f);
    if (lane == 0) g_mask[w] = m;
}

// ---------------- h = X @ W, transposed fp16 out + fused stats --------------
template <int FOUT>
__global__ __launch_bounds__(256) void sgemm_h_kernel(
    const float* __restrict__ X, const float* __restrict__ W,
    const float* __restrict__ as, const float* __restrict__ ad,
    __half* __restrict__ Hh)
{
    constexpr int TN = FOUT / 16;
    __shared__ float sX[16][68];
    __shared__ float sW[16][FOUT + 4];
    __shared__ float sRed1[64][17];
    __shared__ float sRed2[64][17];

    const int tid  = threadIdx.x;
    const int row0 = blockIdx.x * 64;
    const int tr   = tid >> 4;
    const int tc   = tid & 15;

    float acc[4][TN];
#pragma unroll
    for (int r = 0; r < 4; r++)
#pragma unroll
        for (int c = 0; c < TN; c++) acc[r][c] = 0.0f;

    for (int f0 = 0; f0 < 128; f0 += 16) {
        __syncthreads();
        {
            int k  = tid & 15;
            int rr = tid >> 4;
#pragma unroll
            for (int s = 0; s < 4; s++) {
                int r = rr + s * 16;
                sX[k][r] = X[(size_t)(row0 + r) * 128 + f0 + k];
            }
        }
        for (int idx = tid; idx < 16 * FOUT; idx += 256) {
            int kk = idx / FOUT, o = idx % FOUT;
            sW[kk][o] = W[(size_t)(f0 + kk) * FOUT + o];
        }
        __syncthreads();
#pragma unroll
        for (int k = 0; k < 16; k++) {
            float ra[4], rb[TN];
            *(float4*)ra = *(const float4*)&sX[k][tr * 4];
            if (TN == 8) {
                *(float4*)&rb[0] = *(const float4*)&sW[k][tc * 8];
                *(float4*)&rb[4] = *(const float4*)&sW[k][tc * 8 + 4];
            } else {
                *(float4*)&rb[0] = *(const float4*)&sW[k][tc * 4];
            }
#pragma unroll
            for (int r = 0; r < 4; r++)
#pragma unroll
                for (int c = 0; c < TN; c++) acc[r][c] += ra[r] * rb[c];
        }
    }

    float s1[4] = {0, 0, 0, 0}, s2[4] = {0, 0, 0, 0};
#pragma unroll
    for (int c = 0; c < TN; c++) {
        float av = __ldg(as + tc * TN + c);
        float dv = __ldg(ad + tc * TN + c);
#pragma unroll
        for (int r = 0; r < 4; r++) {
            s1[r] += acc[r][c] * av;
            s2[r] += acc[r][c] * dv;
        }
    }
    __syncthreads();
#pragma unroll
    for (int r = 0; r < 4; r++) {
        sRed1[tr * 4 + r][tc] = s1[r];
        sRed2[tr * 4 + r][tc] = s2[r];
    }

    // transposed fp16 store
#pragma unroll
    for (int c = 0; c < TN; c++) {
        int col = tc * TN + c;
        __half2 h01 = __float22half2_rn(make_float2(acc[0][c], acc[1][c]));
        __half2 h23 = __float22half2_rn(make_float2(acc[2][c], acc[3][c]));
        size_t off = (size_t)col * RTOT + row0 + tr * 4;
        *(__half2*)(Hh + off)     = h01;
        *(__half2*)(Hh + off + 2) = h23;
    }

    __syncthreads();
    if (tid < 64) {
        float t1 = 0.0f, t2 = 0.0f;
#pragma unroll
        for (int t = 0; t < 16; t++) { t1 += sRed1[tid][t]; t2 += sRed2[tid][t]; }
        int gr = row0 + tid;
        g_es[gr] = t1; g_r[gr] = __expf(-0.8f * t1);
        g_ed[gr] = t2; g_v[gr] = __expf(t2); g_q[gr] = __expf(0.2f * t2);
    }
}

// ---------------- fused masked-attention, split-j partials ------------------
// Row-normalized P (divide row i by u_i = exp(es_i)):
//   P'_ij = mask ? ((es_i+ed_j>=0) ? v_j : r_i*q_j) : 0
// D(fp32) = (Phi + Plo) @ Hfp16   (P split hi/lo in fp16; H single fp16)
template <int FOUT>
__global__ __launch_bounds__(256, 2) void attn_mma_kernel(
    const __half* __restrict__ Bh)
{
    constexpr int ROWB = 144;                    // P row stride (bytes)
    constexpr uint32_t OFF_ES  = 0;              // 128 f32
    constexpr uint32_t OFF_R   = 512;            // 128 f32
    constexpr uint32_t OFF_SED = 1024;           // 512 f32
    constexpr uint32_t OFF_SV  = OFF_SED + 2048;
    constexpr uint32_t OFF_SQ  = OFF_SV + 2048;
    constexpr uint32_t OFF_PHI = 7680;           // 128 x 72 f16 (padded rows)
    constexpr uint32_t OFF_PLO = OFF_PHI + 128 * ROWB;
    constexpr uint32_t OFF_B   = OFF_PLO + 128 * ROWB;   // 44544
    constexpr uint32_t BUFSTRIDE = (uint32_t)FOUT * 128; // one fp16 tile

    extern __shared__ char smem[];
    const uint32_t sb = smem_to_u32(smem);
    const int tid  = threadIdx.x;
    const int wid  = tid >> 5;
    const int lane = tid & 31;

    const int b    = blockIdx.y;
    const int i0   = blockIdx.x * 128;
    const int z    = blockIdx.z;
    const int base = b * NN;
    const int jbase = base + z * (JT_PER * 64);

    float* ses = (float*)(smem + OFF_ES);
    float* sr  = (float*)(smem + OFF_R);
    float* sed = (float*)(smem + OFF_SED);
    float* sv  = (float*)(smem + OFF_SV);
    float* sq  = (float*)(smem + OFF_SQ);

    // ---- prologue staging ----
    if (tid < 128) {
        int i = base + i0 + tid;
        ses[tid] = g_es[i]; sr[tid] = g_r[i];
    }
#pragma unroll
    for (int t = 0; t < 2; t++) {
        int idx = tid + t * 256;
        sed[idx] = g_ed[jbase + idx];
        sv[idx]  = g_v[jbase + idx];
        sq[idx]  = g_q[jbase + idx];
    }

    // B tile loader: tile l -> buffer buf (cp.async, swizzled 128B rows)
    auto load_B = [&](int l, int buf) {
        const uint32_t dbase = sb + OFF_B + buf * BUFSTRIDE;
        const size_t gcol = (size_t)(jbase + l * 64);
        constexpr int CH = FOUT * 8;   // 16B chunks
#pragma unroll
        for (int t = 0; t < CH / 256; t++) {
            int idx = tid + t * 256;
            int o = idx >> 3, c = idx & 7;
            uint32_t sw = (uint32_t)((c ^ (o & 7)) << 4) + o * 128;
            const char* src = (const char*)(Bh + (size_t)o * RTOT + gcol) + c * 16;
            CP_ASYNC16(dbase + sw, src);
        }
    };

    load_B(0, 0);
    CP_COMMIT();

    // per-thread P-build coordinates
    const int iP = tid >> 1;
    const int jh = tid & 1;

    unsigned mw[JT_PER];
    {
        const unsigned* mrow = g_mask + (size_t)(i0 + iP) * (NN / 32) + z * (JT_PER * 2) + jh;
#pragma unroll
        for (int l = 0; l < JT_PER; l++) mw[l] = mrow[l * 2];
    }

    // ldmatrix fixed addresses
    const int arow  = wid * 16 + (lane & 7) + (((lane >> 3) & 1) << 3);
    const int akoff = (lane >> 4) << 4;
    const uint32_t aHiBase = sb + OFF_PHI + arow * ROWB + akoff;
    const uint32_t aLoBase = sb + OFF_PLO + arow * ROWB + akoff;
    const int brow = (lane & 7) + ((lane >> 4) << 3);
    const int bsel = (lane >> 3) & 1;

    constexpr int NT = FOUT / 8;
    float acc[NT][4];
#pragma unroll
    for (int n = 0; n < NT; n++)
#pragma unroll
        for (int q = 0; q < 4; q++) acc[n][q] = 0.0f;
    float rsum = 0.0f;

    __syncthreads();
    const float esi = ses[iP], ri = sr[iP];
    char* dsthi = smem + OFF_PHI + iP * ROWB + jh * 64;
    char* dstlo = smem + OFF_PLO + iP * ROWB + jh * 64;

    for (int l = 0; l < JT_PER; l++) {
        CP_WAIT0();
        __syncthreads();   // B buf[l&1] ready; prior MMA done everywhere

        if (l + 1 < JT_PER) { load_B(l + 1, (l + 1) & 1); CP_COMMIT(); }

        // build P rows (warp-local ownership), fp16 hi + residual lo
        {
            unsigned m = mw[l];
            const float* sedl = sed + l * 64 + (jh << 5);
            const float* svl  = sv  + l * 64 + (jh << 5);
            const float* sql  = sq  + l * 64 + (jh << 5);
#pragma unroll
            for (int jj = 0; jj < 32; jj += 2) {
                float t0 = esi + sedl[jj];
                float t1 = esi + sedl[jj + 1];
                float v0 = ((m >> jj) & 1u) ? ((t0 >= 0.0f) ? svl[jj] : ri * sql[jj]) : 0.0f;
                float v1 = ((m >> (jj + 1)) & 1u) ? ((t1 >= 0.0f) ? svl[jj + 1] : ri * sql[jj + 1]) : 0.0f;
                v0 = fminf(v0, 60000.0f);
                v1 = fminf(v1, 60000.0f);
                rsum += v0 + v1;
                __half2 hp = __float22half2_rn(make_float2(v0, v1));
                float2 hf = __half22float2(hp);
                __half2 lp = __float22half2_rn(make_float2(v0 - hf.x, v1 - hf.y));
                *(__half2*)(dsthi + jj * 2) = hp;
                *(__half2*)(dstlo + jj * 2) = lp;
            }
        }
        __syncwarp();

        // MMA over buffer l&1
        const uint32_t bB = sb + OFF_B + (l & 1) * BUFSTRIDE;
#pragma unroll
        for (int kk = 0; kk < 4; kk++) {
            uint32_t ah0, ah1, ah2, ah3, al0, al1, al2, al3;
            ldmx4(ah0, ah1, ah2, ah3, aHiBase + kk * 32);
            ldmx4(al0, al1, al2, al3, aLoBase + kk * 32);
            int cIdx = kk * 2 + bsel;
#pragma unroll
            for (int np = 0; np < NT / 2; np++) {
                int r = np * 16 + brow;
                uint32_t ba = bB + r * 128 + (uint32_t)((cIdx ^ (r & 7)) << 4);
                uint32_t bh0, bh1, bh2, bh3;
                ldmx4(bh0, bh1, bh2, bh3, ba);
                mma_f16(acc[np * 2],     ah0, ah1, ah2, ah3, bh0, bh1);
                mma_f16(acc[np * 2],     al0, al1, al2, al3, bh0, bh1);
                mma_f16(acc[np * 2 + 1], ah0, ah1, ah2, ah3, bh2, bh3);
                mma_f16(acc[np * 2 + 1], al0, al1, al2, al3, bh2, bh3);
            }
        }
    }

    // partial row sums
    {
        float tot = rsum + __shfl_xor_sync(0xffffffffu, rsum, 1);
        if (jh == 0) g_ps[z * RTOT + base + i0 + iP] = tot;
    }

    // partial D store (fp32, no div/relu)
    {
        int r0 = wid * 16 + (lane >> 2);
        int r1 = r0 + 8;
        float* p0 = g_pd + (size_t)z * RTOT * 128 + (size_t)(base + i0 + r0) * FOUT + (lane & 3) * 2;
        float* p1 = g_pd + (size_t)z * RTOT * 128 + (size_t)(base + i0 + r1) * FOUT + (lane & 3) * 2;
#pragma unroll
        for (int n = 0; n < NT; n++) {
            *(float2*)(p0 + n * 8) = make_float2(acc[n][0], acc[n][1]);
            *(float2*)(p1 + n * 8) = make_float2(acc[n][2], acc[n][3]);
        }
    }
}

// ---------------- combine partials: out = relu(sum_z D / sum_z s) ----------
template <int FOUT>
__global__ __launch_bounds__(256) void combine_kernel(float* __restrict__ O) {
    int idx = blockIdx.x * 256 + threadIdx.x;
    int row = idx / (FOUT / 4);
    int c4  = idx % (FOUT / 4);
    float rs = 0.0f;
    float4 d = make_float4(0.f, 0.f, 0.f, 0.f);
#pragma unroll
    for (int zz = 0; zz < ZSPLIT; zz++) {
        rs += g_ps[zz * RTOT + row];
        float4 t = *(const float4*)(g_pd + (size_t)zz * RTOT * 128 + (size_t)row * FOUT + c4 * 4);
        d.x += t.x; d.y += t.y; d.z += t.z; d.w += t.w;
    }
    float inv = 1.0f / rs;
    float4 o;
    o.x = fmaxf(d.x * inv, 0.0f);
    o.y = fmaxf(d.y * inv, 0.0f);
    o.z = fmaxf(d.z * inv, 0.0f);
    o.w = fmaxf(d.w * inv, 0.0f);
    *(float4*)(O + (size_t)row * FOUT + c4 * 4) = o;
}

// ---------------- final linear: y[8,128] = X[8,131072] @ Wlin + blin --------
__global__ __launch_bounds__(128) void final_partial_kernel(
    const float* __restrict__ X, const float* __restrict__ Wlin)
{
    int c  = threadIdx.x;
    int s  = blockIdx.x;
    int k0 = s * 512;
    float acc[8] = {0, 0, 0, 0, 0, 0, 0, 0};
    for (int k = k0; k < k0 + 512; k++) {
        float w = Wlin[(size_t)k * 128 + c];
#pragma unroll
        for (int b = 0; b < 8; b++) acc[b] += X[(size_t)b * 131072 + k] * w;
    }
#pragma unroll
    for (int b = 0; b < 8; b++) g_part[s * 1024 + b * 128 + c] = acc[b];
}

__global__ __launch_bounds__(256) void final_reduce_kernel(
    const float* __restrict__ blin, float* __restrict__ out)
{
    int idx = blockIdx.x * 256 + threadIdx.x;
    if (idx < 1024) {
        float s = 0.0f;
        for (int sp = 0; sp < 256; sp++) s += g_part[sp * 1024 + idx];
        out[idx] = s + blin[idx & 127];
    }
}

// ---------------- host driver ------------------------------------------------
extern "C" void kernel_launch(void* const* d_in, const int* in_sizes, int n_in,
                              void* d_out, int out_size)
{
    const float* x    = (const float*)d_in[0];
    const float* adj  = (const float*)d_in[1];
    const float* W1   = (const float*)d_in[2];
    const float* a1s  = (const float*)d_in[3];
    const float* a1d  = (const float*)d_in[4];
    const float* W2   = (const float*)d_in[5];
    const float* a2s  = (const float*)d_in[6];
    const float* a2d  = (const float*)d_in[7];
    const float* W3   = (const float*)d_in[8];
    const float* a3s  = (const float*)d_in[9];
    const float* a3d  = (const float*)d_in[10];
    const float* Wlin = (const float*)d_in[11];
    const float* blin = (const float*)d_in[12];

    void* phh; cudaGetSymbolAddress(&phh, g_hh);
    void* po;  cudaGetSymbolAddress(&po,  g_o);
    __half* hh = (__half*)phh;
    float* obuf = (float*)po;

    constexpr int SM128 = 44544 + 2 * 128 * 128;  // 77312
    constexpr int SM64  = 44544 + 2 * 64 * 128;   // 60928
    cudaFuncSetAttribute(attn_mma_kernel<128>, cudaFuncAttributeMaxDynamicSharedMemorySize, SM128);
    cudaFuncSetAttribute(attn_mma_kernel<64>,  cudaFuncAttributeMaxDynamicSharedMemorySize, SM64);

    build_mask_kernel<<<16384, 256>>>(adj);

    // layer 1 (128 -> 128)
    sgemm_h_kernel<128><<<256, 256>>>(x, W1, a1s, a1d, hh);
    attn_mma_kernel<128><<<dim3(16, 8, ZSPLIT), 256, SM128>>>(hh);
    combine_kernel<128><<<RTOT * 128 / 4 / 256, 256>>>(obuf);

    // layer 2 (128 -> 128)
    sgemm_h_kernel<128><<<256, 256>>>(obuf, W2, a2s, a2d, hh);
    attn_mma_kernel<128><<<dim3(16, 8, ZSPLIT), 256, SM128>>>(hh);
    combine_kernel<128><<<RTOT * 128 / 4 / 256, 256>>>(obuf);

    // layer 3 (128 -> 64)
    sgemm_h_kernel<64><<<256, 256>>>(obuf, W3, a3s, a3d, hh);
    attn_mma_kernel<64><<<dim3(16, 8, ZSPLIT), 256, SM64>>>(hh);
    combine_kernel<64><<<RTOT * 64 / 4 / 256, 256>>>(obuf);

    // final linear
    final_partial_kernel<<<256, 128>>>(obuf, Wlin);
    final_reduce_kernel<<<4, 256>>>(blin, (float*)d_out);
}

// round 6
// speedup vs baseline: 2.5623x; 1.1035x over previous
#include <cuda_runtime.h>
#include <cuda_fp16.h>
#include <cstdint>

// Problem constants (GATAuto: B=8, N=2048, Fin=128, H=[128,128,64], C=128)
#define BB 8
#define NN 2048
#define RTOT (BB*NN)          // 16384 rows
#define ZSPLIT 4
#define JT_PER ((NN/64)/ZSPLIT)   // 8 j-tiles per block

// ---------------- scratch (device globals; no allocation allowed) ----------
__device__ __align__(16) __half g_hh[128 * RTOT];          // h transposed fp16 [o][row]
__device__ __align__(16) float  g_o[RTOT * 128];           // layer outputs (row-major)
__device__ __align__(16) float  g_pd[(size_t)ZSPLIT * RTOT * 128];  // partial D
__device__ float    g_ps[ZSPLIT * RTOT];                   // partial row sums
__device__ float    g_es[RTOT], g_r[RTOT];                 // es, exp(-0.8 es)
__device__ float    g_ed[RTOT], g_v[RTOT], g_q[RTOT];      // ed, exp(ed), exp(0.2 ed)
__device__ unsigned g_mask[NN * (NN / 32)];                // adjacency bitmask, 512KB
__device__ float    g_part[256 * 1024];                    // final-linear split-K partials

// ======================= warp MMA helpers (baseline PTX) =====================
__device__ __forceinline__ uint32_t smem_to_u32(const void* p) {
    uint32_t a;
    asm("{ .reg .u64 t; cvta.to.shared.u64 t, %1; cvt.u32.u64 %0, t; }" : "=r"(a) : "l"(p));
    return a;
}
__device__ __forceinline__ void ldmx4(uint32_t& r0, uint32_t& r1, uint32_t& r2, uint32_t& r3,
                                      uint32_t addr) {
    asm volatile("ldmatrix.sync.aligned.m8n8.x4.shared.b16 {%0,%1,%2,%3}, [%4];"
                 : "=r"(r0), "=r"(r1), "=r"(r2), "=r"(r3) : "r"(addr));
}
__device__ __forceinline__ void mma_f16(float* d, uint32_t a0, uint32_t a1, uint32_t a2,
                                        uint32_t a3, uint32_t b0, uint32_t b1) {
    asm volatile("mma.sync.aligned.m16n8k16.row.col.f32.f16.f16.f32 "
                 "{%0,%1,%2,%3}, {%4,%5,%6,%7}, {%8,%9}, {%0,%1,%2,%3};"
                 : "+f"(d[0]), "+f"(d[1]), "+f"(d[2]), "+f"(d[3])
                 : "r"(a0), "r"(a1), "r"(a2), "r"(a3), "r"(b0), "r"(b1));
}
#define CP_ASYNC16(dst, src) \
    asm volatile("cp.async.ca.shared.global [%0], [%1], 16;" :: "r"(dst), "l"(src))
#define CP_COMMIT() asm volatile("cp.async.commit_group;" ::: "memory")
#define CP_WAIT0()  asm volatile("cp.async.wait_group 0;" ::: "memory")

// ---------------- adjacency bitmask ----------------------------------------
__global__ void build_mask_kernel(const float* __restrict__ adj) {
    int w    = blockIdx.x * 8 + (threadIdx.x >> 5);
    int lane = threadIdx.x & 31;
    int row  = w >> 6;
    int wc   = w & 63;
    float av = adj[(size_t)row * NN + wc * 32 + lane];
    unsigned m = __ballot_sync(0xffffffffu, av > 0.0f);
    if (lane == 0) g_mask[w] = m;
}

// ---------------- h = X @ W, transposed fp16 out + fused stats --------------
// Single-sync double-buffered pipeline (reg prefetch -> smem).
template <int FOUT>
__global__ __launch_bounds__(256) void sgemm_h_kernel(
    const float* __restrict__ X, const float* __restrict__ W,
    const float* __restrict__ as, const float* __restrict__ ad,
    __half* __restrict__ Hh)
{
    constexpr int TN = FOUT / 16;
    __shared__ float sX[2][16][68];
    __shared__ float sW[2][16][FOUT + 4];
    __shared__ float sRed1[64][17];
    __shared__ float sRed2[64][17];

    const int tid  = threadIdx.x;
    const int row0 = blockIdx.x * 64;
    const int tr   = tid >> 4;
    const int tc   = tid & 15;

    // loader coordinates
    const int lk = tid & 15;   // k within chunk
    const int lr = tid >> 4;   // base row (4 rows: lr + s*16)

    float xr[4], wr[TN];
    auto ldg_chunk = [&](int f0) {
#pragma unroll
        for (int s = 0; s < 4; s++)
            xr[s] = X[(size_t)(row0 + lr + s * 16) * 128 + f0 + lk];
#pragma unroll
        for (int t = 0; t < TN; t++) {
            int idx = tid + t * 256;
            wr[t] = W[(size_t)(f0 + idx / FOUT) * FOUT + idx % FOUT];
        }
    };
    auto st_chunk = [&](int buf) {
#pragma unroll
        for (int s = 0; s < 4; s++) sX[buf][lk][lr + s * 16] = xr[s];
#pragma unroll
        for (int t = 0; t < TN; t++) {
            int idx = tid + t * 256;
            sW[buf][idx / FOUT][idx % FOUT] = wr[t];
        }
    };

    float acc[4][TN];
#pragma unroll
    for (int r = 0; r < 4; r++)
#pragma unroll
        for (int c = 0; c < TN; c++) acc[r][c] = 0.0f;

    ldg_chunk(0);
    st_chunk(0);
    __syncthreads();

    for (int c8 = 0; c8 < 8; c8++) {
        if (c8 < 7) ldg_chunk((c8 + 1) * 16);
        const int buf = c8 & 1;
#pragma unroll
        for (int k = 0; k < 16; k++) {
            float ra[4], rb[TN];
            *(float4*)ra = *(const float4*)&sX[buf][k][tr * 4];
            if (TN == 8) {
                *(float4*)&rb[0] = *(const float4*)&sW[buf][k][tc * 8];
                *(float4*)&rb[4] = *(const float4*)&sW[buf][k][tc * 8 + 4];
            } else {
                *(float4*)&rb[0] = *(const float4*)&sW[buf][k][tc * 4];
            }
#pragma unroll
            for (int r = 0; r < 4; r++)
#pragma unroll
                for (int c = 0; c < TN; c++) acc[r][c] += ra[r] * rb[c];
        }
        if (c8 < 7) st_chunk(buf ^ 1);
        __syncthreads();
    }

    float s1[4] = {0, 0, 0, 0}, s2[4] = {0, 0, 0, 0};
#pragma unroll
    for (int c = 0; c < TN; c++) {
        float av = __ldg(as + tc * TN + c);
        float dv = __ldg(ad + tc * TN + c);
#pragma unroll
        for (int r = 0; r < 4; r++) {
            s1[r] += acc[r][c] * av;
            s2[r] += acc[r][c] * dv;
        }
    }
#pragma unroll
    for (int r = 0; r < 4; r++) {
        sRed1[tr * 4 + r][tc] = s1[r];
        sRed2[tr * 4 + r][tc] = s2[r];
    }

    // transposed fp16 store
#pragma unroll
    for (int c = 0; c < TN; c++) {
        int col = tc * TN + c;
        __half2 h01 = __float22half2_rn(make_float2(acc[0][c], acc[1][c]));
        __half2 h23 = __float22half2_rn(make_float2(acc[2][c], acc[3][c]));
        size_t off = (size_t)col * RTOT + row0 + tr * 4;
        *(__half2*)(Hh + off)     = h01;
        *(__half2*)(Hh + off + 2) = h23;
    }

    __syncthreads();
    if (tid < 64) {
        float t1 = 0.0f, t2 = 0.0f;
#pragma unroll
        for (int t = 0; t < 16; t++) { t1 += sRed1[tid][t]; t2 += sRed2[tid][t]; }
        int gr = row0 + tid;
        g_es[gr] = t1; g_r[gr] = __expf(-0.8f * t1);
        g_ed[gr] = t2; g_v[gr] = __expf(t2); g_q[gr] = __expf(0.2f * t2);
    }
}

// ---------------- fused masked-attention, split-j partials ------------------
// Row-normalized P (divide row i by u_i = exp(es_i)):
//   P'_ij = mask ? ((es_i+ed_j>=0) ? v_j : r_i*q_j) : 0
// D(fp32) = P(fp16) @ H(fp16)  — single product
template <int FOUT>
__global__ __launch_bounds__(256, 2) void attn_mma_kernel(
    const __half* __restrict__ Bh)
{
    constexpr int ROWB = 144;                    // P row stride (bytes)
    constexpr uint32_t OFF_ES  = 0;              // 128 f32
    constexpr uint32_t OFF_R   = 512;            // 128 f32
    constexpr uint32_t OFF_SED = 1024;           // 512 f32
    constexpr uint32_t OFF_SV  = OFF_SED + 2048;
    constexpr uint32_t OFF_SQ  = OFF_SV + 2048;
    constexpr uint32_t OFF_PHI = 7680;           // 128 x 72 f16 (padded rows)
    constexpr uint32_t OFF_B   = OFF_PHI + 128 * ROWB;   // 26112
    constexpr uint32_t BUFSTRIDE = (uint32_t)FOUT * 128; // one fp16 tile

    extern __shared__ char smem[];
    const uint32_t sb = smem_to_u32(smem);
    const int tid  = threadIdx.x;
    const int wid  = tid >> 5;
    const int lane = tid & 31;

    const int b    = blockIdx.y;
    const int i0   = blockIdx.x * 128;
    const int z    = blockIdx.z;
    const int base = b * NN;
    const int jbase = base + z * (JT_PER * 64);

    float* ses = (float*)(smem + OFF_ES);
    float* sr  = (float*)(smem + OFF_R);
    float* sed = (float*)(smem + OFF_SED);
    float* sv  = (float*)(smem + OFF_SV);
    float* sq  = (float*)(smem + OFF_SQ);

    // ---- prologue staging ----
    if (tid < 128) {
        int i = base + i0 + tid;
        ses[tid] = g_es[i]; sr[tid] = g_r[i];
    }
#pragma unroll
    for (int t = 0; t < 2; t++) {
        int idx = tid + t * 256;
        sed[idx] = g_ed[jbase + idx];
        sv[idx]  = g_v[jbase + idx];
        sq[idx]  = g_q[jbase + idx];
    }

    // B tile loader: tile l -> buffer buf (cp.async, swizzled 128B rows)
    auto load_B = [&](int l, int buf) {
        const uint32_t dbase = sb + OFF_B + buf * BUFSTRIDE;
        const size_t gcol = (size_t)(jbase + l * 64);
        constexpr int CH = FOUT * 8;   // 16B chunks
#pragma unroll
        for (int t = 0; t < CH / 256; t++) {
            int idx = tid + t * 256;
            int o = idx >> 3, c = idx & 7;
            uint32_t sw = (uint32_t)((c ^ (o & 7)) << 4) + o * 128;
            const char* src = (const char*)(Bh + (size_t)o * RTOT + gcol) + c * 16;
            CP_ASYNC16(dbase + sw, src);
        }
    };

    load_B(0, 0);
    CP_COMMIT();

    // per-thread P-build coordinates
    const int iP = tid >> 1;
    const int jh = tid & 1;

    unsigned mw[JT_PER];
    {
        const unsigned* mrow = g_mask + (size_t)(i0 + iP) * (NN / 32) + z * (JT_PER * 2) + jh;
#pragma unroll
        for (int l = 0; l < JT_PER; l++) mw[l] = mrow[l * 2];
    }

    // ldmatrix fixed addresses
    const int arow  = wid * 16 + (lane & 7) + (((lane >> 3) & 1) << 3);
    const int akoff = (lane >> 4) << 4;
    const uint32_t aHiBase = sb + OFF_PHI + arow * ROWB + akoff;
    const int brow = (lane & 7) + ((lane >> 4) << 3);
    const int bsel = (lane >> 3) & 1;

    constexpr int NT = FOUT / 8;
    float acc[NT][4];
#pragma unroll
    for (int n = 0; n < NT; n++)
#pragma unroll
        for (int q = 0; q < 4; q++) acc[n][q] = 0.0f;
    float rsum = 0.0f;

    __syncthreads();
    const float esi = ses[iP], ri = sr[iP];
    char* dsthi = smem + OFF_PHI + iP * ROWB + jh * 64;

    for (int l = 0; l < JT_PER; l++) {
        CP_WAIT0();
        __syncthreads();   // B buf[l&1] ready; prior MMA done everywhere

        if (l + 1 < JT_PER) { load_B(l + 1, (l + 1) & 1); CP_COMMIT(); }

        // build P rows (warp-local ownership), fp16 single
        {
            unsigned m = mw[l];
            const float* sedl = sed + l * 64 + (jh << 5);
            const float* svl  = sv  + l * 64 + (jh << 5);
            const float* sql  = sq  + l * 64 + (jh << 5);
#pragma unroll
            for (int jj = 0; jj < 32; jj += 2) {
                float t0 = esi + sedl[jj];
                float t1 = esi + sedl[jj + 1];
                float v0 = ((m >> jj) & 1u) ? ((t0 >= 0.0f) ? svl[jj] : ri * sql[jj]) : 0.0f;
                float v1 = ((m >> (jj + 1)) & 1u) ? ((t1 >= 0.0f) ? svl[jj + 1] : ri * sql[jj + 1]) : 0.0f;
                v0 = fminf(v0, 60000.0f);
                v1 = fminf(v1, 60000.0f);
                rsum += v0 + v1;
                *(__half2*)(dsthi + jj * 2) = __float22half2_rn(make_float2(v0, v1));
            }
        }
        __syncwarp();

        // MMA over buffer l&1
        const uint32_t bB = sb + OFF_B + (l & 1) * BUFSTRIDE;
#pragma unroll
        for (int kk = 0; kk < 4; kk++) {
            uint32_t ah0, ah1, ah2, ah3;
            ldmx4(ah0, ah1, ah2, ah3, aHiBase + kk * 32);
            int cIdx = kk * 2 + bsel;
#pragma unroll
            for (int np = 0; np < NT / 2; np++) {
                int r = np * 16 + brow;
                uint32_t ba = bB + r * 128 + (uint32_t)((cIdx ^ (r & 7)) << 4);
                uint32_t bh0, bh1, bh2, bh3;
                ldmx4(bh0, bh1, bh2, bh3, ba);
                mma_f16(acc[np * 2],     ah0, ah1, ah2, ah3, bh0, bh1);
                mma_f16(acc[np * 2 + 1], ah0, ah1, ah2, ah3, bh2, bh3);
            }
        }
    }

    // partial row sums
    {
        float tot = rsum + __shfl_xor_sync(0xffffffffu, rsum, 1);
        if (jh == 0) g_ps[z * RTOT + base + i0 + iP] = tot;
    }

    // partial D store (fp32, no div/relu)
    {
        int r0 = wid * 16 + (lane >> 2);
        int r1 = r0 + 8;
        float* p0 = g_pd + (size_t)z * RTOT * 128 + (size_t)(base + i0 + r0) * FOUT + (lane & 3) * 2;
        float* p1 = g_pd + (size_t)z * RTOT * 128 + (size_t)(base + i0 + r1) * FOUT + (lane & 3) * 2;
#pragma unroll
        for (int n = 0; n < NT; n++) {
            *(float2*)(p0 + n * 8) = make_float2(acc[n][0], acc[n][1]);
            *(float2*)(p1 + n * 8) = make_float2(acc[n][2], acc[n][3]);
        }
    }
}

// ---------------- combine partials: out = relu(sum_z D / sum_z s) ----------
template <int FOUT>
__global__ __launch_bounds__(256) void combine_kernel(float* __restrict__ O) {
    int idx = blockIdx.x * 256 + threadIdx.x;
    int row = idx / (FOUT / 4);
    int c4  = idx % (FOUT / 4);
    float rs = 0.0f;
    float4 d = make_float4(0.f, 0.f, 0.f, 0.f);
#pragma unroll
    for (int zz = 0; zz < ZSPLIT; zz++) {
        rs += g_ps[zz * RTOT + row];
        float4 t = *(const float4*)(g_pd + (size_t)zz * RTOT * 128 + (size_t)row * FOUT + c4 * 4);
        d.x += t.x; d.y += t.y; d.z += t.z; d.w += t.w;
    }
    float inv = 1.0f / rs;
    float4 o;
    o.x = fmaxf(d.x * inv, 0.0f);
    o.y = fmaxf(d.y * inv, 0.0f);
    o.z = fmaxf(d.z * inv, 0.0f);
    o.w = fmaxf(d.w * inv, 0.0f);
    *(float4*)(O + (size_t)row * FOUT + c4 * 4) = o;
}

// ---------------- final linear: y[8,128] = X[8,131072] @ Wlin + blin --------
__global__ __launch_bounds__(128) void final_partial_kernel(
    const float* __restrict__ X, const float* __restrict__ Wlin)
{
    int c  = threadIdx.x;
    int s  = blockIdx.x;
    int k0 = s * 512;
    float acc[8] = {0, 0, 0, 0, 0, 0, 0, 0};
    for (int k = k0; k < k0 + 512; k++) {
        float w = Wlin[(size_t)k * 128 + c];
#pragma unroll
        for (int b = 0; b < 8; b++) acc[b] += X[(size_t)b * 131072 + k] * w;
    }
#pragma unroll
    for (int b = 0; b < 8; b++) g_part[s * 1024 + b * 128 + c] = acc[b];
}

__global__ __launch_bounds__(256) void final_reduce_kernel(
    const float* __restrict__ blin, float* __restrict__ out)
{
    int idx = blockIdx.x * 256 + threadIdx.x;
    if (idx < 1024) {
        float s = 0.0f;
        for (int sp = 0; sp < 256; sp++) s += g_part[sp * 1024 + idx];
        out[idx] = s + blin[idx & 127];
    }
}

// ---------------- host driver ------------------------------------------------
extern "C" void kernel_launch(void* const* d_in, const int* in_sizes, int n_in,
                              void* d_out, int out_size)
{
    const float* x    = (const float*)d_in[0];
    const float* adj  = (const float*)d_in[1];
    const float* W1   = (const float*)d_in[2];
    const float* a1s  = (const float*)d_in[3];
    const float* a1d  = (const float*)d_in[4];
    const float* W2   = (const float*)d_in[5];
    const float* a2s  = (const float*)d_in[6];
    const float* a2d  = (const float*)d_in[7];
    const float* W3   = (const float*)d_in[8];
    const float* a3s  = (const float*)d_in[9];
    const float* a3d  = (const float*)d_in[10];
    const float* Wlin = (const float*)d_in[11];
    const float* blin = (const float*)d_in[12];

    void* phh; cudaGetSymbolAddress(&phh, g_hh);
    void* po;  cudaGetSymbolAddress(&po,  g_o);
    __half* hh = (__half*)phh;
    float* obuf = (float*)po;

    constexpr int SM128 = 26112 + 2 * 128 * 128;  // 58880
    constexpr int SM64  = 26112 + 2 * 64 * 128;   // 42496
    cudaFuncSetAttribute(attn_mma_kernel<128>, cudaFuncAttributeMaxDynamicSharedMemorySize, SM128);
    cudaFuncSetAttribute(attn_mma_kernel<64>,  cudaFuncAttributeMaxDynamicSharedMemorySize, SM64);

    build_mask_kernel<<<16384, 256>>>(adj);

    // layer 1 (128 -> 128)
    sgemm_h_kernel<128><<<256, 256>>>(x, W1, a1s, a1d, hh);
    attn_mma_kernel<128><<<dim3(16, 8, ZSPLIT), 256, SM128>>>(hh);
    combine_kernel<128><<<RTOT * 128 / 4 / 256, 256>>>(obuf);

    // layer 2 (128 -> 128)
    sgemm_h_kernel<128><<<256, 256>>>(obuf, W2, a2s, a2d, hh);
    attn_mma_kernel<128><<<dim3(16, 8, ZSPLIT), 256, SM128>>>(hh);
    combine_kernel<128><<<RTOT * 128 / 4 / 256, 256>>>(obuf);

    // layer 3 (128 -> 64)
    sgemm_h_kernel<64><<<256, 256>>>(obuf, W3, a3s, a3d, hh);
    attn_mma_kernel<64><<<dim3(16, 8, ZSPLIT), 256, SM64>>>(hh);
    combine_kernel<64><<<RTOT * 64 / 4 / 256, 256>>>(obuf);

    // final linear
    final_partial_kernel<<<256, 128>>>(obuf, Wlin);
    final_reduce_kernel<<<4, 256>>>(blin, (float*)d_out);
}

// round 7
// speedup vs baseline: 3.1327x; 1.2226x over previous
#include <cuda_runtime.h>
#include <cuda_fp16.h>
#include <cstdint>

// Problem constants (GATAuto: B=8, N=2048, Fin=128, H=[128,128,64], C=128)
#define BB 8
#define NN 2048
#define RTOT (BB*NN)          // 16384 rows
#define ZSPLIT 4
#define JT_PER ((NN/64)/ZSPLIT)   // 8 j-tiles per block

// ---------------- scratch (device globals; no allocation allowed) ----------
__device__ __align__(16) __half g_hh[128 * RTOT];          // h transposed fp16 [o][row]
__device__ __align__(16) float  g_o[RTOT * 128];           // layer outputs (row-major)
__device__ __align__(16) float  g_pd[(size_t)ZSPLIT * RTOT * 128];  // partial D
__device__ float    g_ps[ZSPLIT * RTOT];                   // partial row sums
__device__ float    g_es[RTOT], g_r[RTOT];                 // es, exp(-0.8 es)
__device__ float    g_ed[RTOT], g_v[RTOT], g_q[RTOT];      // ed, exp(ed), exp(0.2 ed)
__device__ unsigned g_mask[NN * (NN / 32)];                // adjacency bitmask, 512KB
__device__ float    g_part[256 * 1024];                    // final-linear split-K partials

// ======================= warp MMA helpers (baseline PTX) =====================
__device__ __forceinline__ uint32_t smem_to_u32(const void* p) {
    uint32_t a;
    asm("{ .reg .u64 t; cvta.to.shared.u64 t, %1; cvt.u32.u64 %0, t; }" : "=r"(a) : "l"(p));
    return a;
}
__device__ __forceinline__ void ldmx4(uint32_t& r0, uint32_t& r1, uint32_t& r2, uint32_t& r3,
                                      uint32_t addr) {
    asm volatile("ldmatrix.sync.aligned.m8n8.x4.shared.b16 {%0,%1,%2,%3}, [%4];"
                 : "=r"(r0), "=r"(r1), "=r"(r2), "=r"(r3) : "r"(addr));
}
__device__ __forceinline__ void mma_f16(float* d, uint32_t a0, uint32_t a1, uint32_t a2,
                                        uint32_t a3, uint32_t b0, uint32_t b1) {
    asm volatile("mma.sync.aligned.m16n8k16.row.col.f32.f16.f16.f32 "
                 "{%0,%1,%2,%3}, {%4,%5,%6,%7}, {%8,%9}, {%0,%1,%2,%3};"
                 : "+f"(d[0]), "+f"(d[1]), "+f"(d[2]), "+f"(d[3])
                 : "r"(a0), "r"(a1), "r"(a2), "r"(a3), "r"(b0), "r"(b1));
}
#define CP_ASYNC16(dst, src) \
    asm volatile("cp.async.ca.shared.global [%0], [%1], 16;" :: "r"(dst), "l"(src))
#define CP_COMMIT() asm volatile("cp.async.commit_group;" ::: "memory")
#define CP_WAIT0()  asm volatile("cp.async.wait_group 0;" ::: "memory")

// fp16x2 packed ops on u32 registers
__device__ __forceinline__ uint32_t hadd2u(uint32_t a, uint32_t b) {
    uint32_t d; asm("add.f16x2 %0, %1, %2;" : "=r"(d) : "r"(a), "r"(b)); return d;
}
__device__ __forceinline__ uint32_t hmul2u(uint32_t a, uint32_t b) {
    uint32_t d; asm("mul.f16x2 %0, %1, %2;" : "=r"(d) : "r"(a), "r"(b)); return d;
}
__device__ __forceinline__ uint32_t hmin2u(uint32_t a, uint32_t b) {
    uint32_t d; asm("min.f16x2 %0, %1, %2;" : "=r"(d) : "r"(a), "r"(b)); return d;
}
__device__ __forceinline__ uint32_t hge2_mask(uint32_t a, uint32_t b) {
    uint32_t d; asm("set.ge.u32.f16x2 %0, %1, %2;" : "=r"(d) : "r"(a), "r"(b)); return d;
}

// ---------------- adjacency bitmask ----------------------------------------
__global__ void build_mask_kernel(const float* __restrict__ adj) {
    int w    = blockIdx.x * 8 + (threadIdx.x >> 5);
    int lane = threadIdx.x & 31;
    int row  = w >> 6;
    int wc   = w & 63;
    float av = adj[(size_t)row * NN + wc * 32 + lane];
    unsigned m = __ballot_sync(0xffffffffu, av > 0.0f);
    if (lane == 0) g_mask[w] = m;
}

// ---------------- h = X @ W, transposed fp16 out + fused stats --------------
// Single-sync double-buffered pipeline (reg prefetch -> smem).
template <int FOUT>
__global__ __launch_bounds__(256) void sgemm_h_kernel(
    const float* __restrict__ X, const float* __restrict__ W,
    const float* __restrict__ as, const float* __restrict__ ad,
    __half* __restrict__ Hh)
{
    constexpr int TN = FOUT / 16;
    __shared__ float sX[2][16][68];
    __shared__ float sW[2][16][FOUT + 4];
    __shared__ float sRed1[64][17];
    __shared__ float sRed2[64][17];

    const int tid  = threadIdx.x;
    const int row0 = blockIdx.x * 64;
    const int tr   = tid >> 4;
    const int tc   = tid & 15;

    const int lk = tid & 15;
    const int lr = tid >> 4;

    float xr[4], wr[TN];
    auto ldg_chunk = [&](int f0) {
#pragma unroll
        for (int s = 0; s < 4; s++)
            xr[s] = X[(size_t)(row0 + lr + s * 16) * 128 + f0 + lk];
#pragma unroll
        for (int t = 0; t < TN; t++) {
            int idx = tid + t * 256;
            wr[t] = W[(size_t)(f0 + idx / FOUT) * FOUT + idx % FOUT];
        }
    };
    auto st_chunk = [&](int buf) {
#pragma unroll
        for (int s = 0; s < 4; s++) sX[buf][lk][lr + s * 16] = xr[s];
#pragma unroll
        for (int t = 0; t < TN; t++) {
            int idx = tid + t * 256;
            sW[buf][idx / FOUT][idx % FOUT] = wr[t];
        }
    };

    float acc[4][TN];
#pragma unroll
    for (int r = 0; r < 4; r++)
#pragma unroll
        for (int c = 0; c < TN; c++) acc[r][c] = 0.0f;

    ldg_chunk(0);
    st_chunk(0);
    __syncthreads();

    for (int c8 = 0; c8 < 8; c8++) {
        if (c8 < 7) ldg_chunk((c8 + 1) * 16);
        const int buf = c8 & 1;
#pragma unroll
        for (int k = 0; k < 16; k++) {
            float ra[4], rb[TN];
            *(float4*)ra = *(const float4*)&sX[buf][k][tr * 4];
            if (TN == 8) {
                *(float4*)&rb[0] = *(const float4*)&sW[buf][k][tc * 8];
                *(float4*)&rb[4] = *(const float4*)&sW[buf][k][tc * 8 + 4];
            } else {
                *(float4*)&rb[0] = *(const float4*)&sW[buf][k][tc * 4];
            }
#pragma unroll
            for (int r = 0; r < 4; r++)
#pragma unroll
                for (int c = 0; c < TN; c++) acc[r][c] += ra[r] * rb[c];
        }
        if (c8 < 7) st_chunk(buf ^ 1);
        __syncthreads();
    }

    float s1[4] = {0, 0, 0, 0}, s2[4] = {0, 0, 0, 0};
#pragma unroll
    for (int c = 0; c < TN; c++) {
        float av = __ldg(as + tc * TN + c);
        float dv = __ldg(ad + tc * TN + c);
#pragma unroll
        for (int r = 0; r < 4; r++) {
            s1[r] += acc[r][c] * av;
            s2[r] += acc[r][c] * dv;
        }
    }
#pragma unroll
    for (int r = 0; r < 4; r++) {
        sRed1[tr * 4 + r][tc] = s1[r];
        sRed2[tr * 4 + r][tc] = s2[r];
    }

    // transposed fp16 store
#pragma unroll
    for (int c = 0; c < TN; c++) {
        int col = tc * TN + c;
        __half2 h01 = __float22half2_rn(make_float2(acc[0][c], acc[1][c]));
        __half2 h23 = __float22half2_rn(make_float2(acc[2][c], acc[3][c]));
        size_t off = (size_t)col * RTOT + row0 + tr * 4;
        *(__half2*)(Hh + off)     = h01;
        *(__half2*)(Hh + off + 2) = h23;
    }

    __syncthreads();
    if (tid < 64) {
        float t1 = 0.0f, t2 = 0.0f;
#pragma unroll
        for (int t = 0; t < 16; t++) { t1 += sRed1[tid][t]; t2 += sRed2[tid][t]; }
        int gr = row0 + tid;
        g_es[gr] = t1; g_r[gr] = __expf(-0.8f * t1);
        g_ed[gr] = t2; g_v[gr] = __expf(t2); g_q[gr] = __expf(0.2f * t2);
    }
}

// ---------------- fused masked-attention, split-j partials ------------------
// Row-normalized P (divide row i by u_i = exp(es_i)):
//   P'_ij = mask ? ((es_i+ed_j>=0) ? v_j : r_i*q_j) : 0      (fp16x2 build)
// D(fp32) = P(fp16) @ H(fp16); row sums via all-ones MMA fragment.
template <int FOUT>
__global__ __launch_bounds__(256, 2) void attn_mma_kernel(
    const __half* __restrict__ Bh)
{
    constexpr int ROWB = 144;                    // P row stride (bytes)
    constexpr uint32_t OFF_ES  = 0;              // 128 f32
    constexpr uint32_t OFF_R   = 512;            // 128 f32
    constexpr uint32_t OFF_EDH = 1024;           // 512 half
    constexpr uint32_t OFF_VH  = 2048;           // 512 half
    constexpr uint32_t OFF_QH  = 3072;           // 512 half
    constexpr uint32_t OFF_PHI = 4096;           // 128 x 72 f16 (padded rows)
    constexpr uint32_t OFF_B   = OFF_PHI + 128 * ROWB;   // 22528
    constexpr uint32_t BUFSTRIDE = (uint32_t)FOUT * 128; // one fp16 tile
    constexpr uint32_t ONES  = 0x3C003C00u;      // fp16x2 {1,1}
    constexpr uint32_t CLAMP = 0x7B537B53u;      // fp16x2 {60000,60000}

    extern __shared__ char smem[];
    const uint32_t sb = smem_to_u32(smem);
    const int tid  = threadIdx.x;
    const int wid  = tid >> 5;
    const int lane = tid & 31;

    const int b    = blockIdx.y;
    const int i0   = blockIdx.x * 128;
    const int z    = blockIdx.z;
    const int base = b * NN;
    const int jbase = base + z * (JT_PER * 64);

    float*  ses  = (float*)(smem + OFF_ES);
    float*  sr   = (float*)(smem + OFF_R);
    __half* sedh = (__half*)(smem + OFF_EDH);
    __half* svh  = (__half*)(smem + OFF_VH);
    __half* sqh  = (__half*)(smem + OFF_QH);

    // ---- prologue staging ----
    if (tid < 128) {
        int i = base + i0 + tid;
        ses[tid] = g_es[i]; sr[tid] = g_r[i];
    }
#pragma unroll
    for (int t = 0; t < 2; t++) {
        int idx = tid + t * 256;
        sedh[idx] = __float2half(g_ed[jbase + idx]);
        svh[idx]  = __float2half(fminf(g_v[jbase + idx], 60000.0f));
        sqh[idx]  = __float2half(g_q[jbase + idx]);
    }

    // B tile loader: tile l -> buffer buf (cp.async, swizzled 128B rows)
    auto load_B = [&](int l, int buf) {
        const uint32_t dbase = sb + OFF_B + buf * BUFSTRIDE;
        const size_t gcol = (size_t)(jbase + l * 64);
        constexpr int CH = FOUT * 8;   // 16B chunks
#pragma unroll
        for (int t = 0; t < CH / 256; t++) {
            int idx = tid + t * 256;
            int o = idx >> 3, c = idx & 7;
            uint32_t sw = (uint32_t)((c ^ (o & 7)) << 4) + o * 128;
            const char* src = (const char*)(Bh + (size_t)o * RTOT + gcol) + c * 16;
            CP_ASYNC16(dbase + sw, src);
        }
    };

    load_B(0, 0);
    CP_COMMIT();

    // per-thread P-build coordinates
    const int iP = tid >> 1;
    const int jh = tid & 1;

    unsigned mw[JT_PER];
    {
        const unsigned* mrow = g_mask + (size_t)(i0 + iP) * (NN / 32) + z * (JT_PER * 2) + jh;
#pragma unroll
        for (int l = 0; l < JT_PER; l++) mw[l] = mrow[l * 2];
    }

    // ldmatrix fixed addresses
    const int arow  = wid * 16 + (lane & 7) + (((lane >> 3) & 1) << 3);
    const int akoff = (lane >> 4) << 4;
    const uint32_t aHiBase = sb + OFF_PHI + arow * ROWB + akoff;
    const int brow = (lane & 7) + ((lane >> 4) << 3);
    const int bsel = (lane >> 3) & 1;

    constexpr int NT = FOUT / 8;
    float acc[NT][4];
#pragma unroll
    for (int n = 0; n < NT; n++)
#pragma unroll
        for (int q = 0; q < 4; q++) acc[n][q] = 0.0f;
    float accRS[4] = {0.f, 0.f, 0.f, 0.f};   // row sums via ones-MMA

    __syncthreads();
    // packed per-thread constants
    uint32_t es2, ri2;
    {
        __half eh = __float2half(ses[iP]);
        __half rh = __float2half(fminf(sr[iP], 60000.0f));
        uint16_t eu = __half_as_ushort(eh), ru = __half_as_ushort(rh);
        es2 = (uint32_t)eu | ((uint32_t)eu << 16);
        ri2 = (uint32_t)ru | ((uint32_t)ru << 16);
    }
    char* dsthi = smem + OFF_PHI + iP * ROWB + jh * 64;

    for (int l = 0; l < JT_PER; l++) {
        CP_WAIT0();
        __syncthreads();   // B buf[l&1] ready; prior MMA done everywhere

        if (l + 1 < JT_PER) { load_B(l + 1, (l + 1) & 1); CP_COMMIT(); }

        // build P rows (warp-local ownership), fp16x2 vectorized
        {
            const unsigned m = mw[l];
            const __half* edl = sedh + l * 64 + (jh << 5);
            const __half* vl  = svh  + l * 64 + (jh << 5);
            const __half* ql  = sqh  + l * 64 + (jh << 5);
#pragma unroll
            for (int jj = 0; jj < 32; jj += 4) {
                uint2 ed = *(const uint2*)(edl + jj);
                uint2 vv = *(const uint2*)(vl + jj);
                uint2 qq = *(const uint2*)(ql + jj);
                uint32_t t0 = hadd2u(es2, ed.x);
                uint32_t t1 = hadd2u(es2, ed.y);
                uint32_t ge0 = hge2_mask(t0, 0u);
                uint32_t ge1 = hge2_mask(t1, 0u);
                uint32_t lo0 = hmul2u(ri2, qq.x);
                uint32_t lo1 = hmul2u(ri2, qq.y);
                uint32_t a0 = (vv.x & ge0) | (lo0 & ~ge0);
                uint32_t a1 = (vv.y & ge1) | (lo1 & ~ge1);
                uint32_t mm = m >> jj;
                a0 &= ((mm & 1u) * 0xFFFFu) | (((mm >> 1) & 1u) * 0xFFFF0000u);
                a1 &= (((mm >> 2) & 1u) * 0xFFFFu) | (((mm >> 3) & 1u) * 0xFFFF0000u);
                a0 = hmin2u(a0, CLAMP);
                a1 = hmin2u(a1, CLAMP);
                *(uint2*)(dsthi + jj * 2) = make_uint2(a0, a1);
            }
        }
        __syncwarp();

        // MMA over buffer l&1
        const uint32_t bB = sb + OFF_B + (l & 1) * BUFSTRIDE;
#pragma unroll
        for (int kk = 0; kk < 4; kk++) {
            uint32_t ah0, ah1, ah2, ah3;
            ldmx4(ah0, ah1, ah2, ah3, aHiBase + kk * 32);
            // row-sum tile: B = all ones (constant fragment, no loads)
            mma_f16(accRS, ah0, ah1, ah2, ah3, ONES, ONES);
            int cIdx = kk * 2 + bsel;
#pragma unroll
            for (int np = 0; np < NT / 2; np++) {
                int r = np * 16 + brow;
                uint32_t ba = bB + r * 128 + (uint32_t)((cIdx ^ (r & 7)) << 4);
                uint32_t bh0, bh1, bh2, bh3;
                ldmx4(bh0, bh1, bh2, bh3, ba);
                mma_f16(acc[np * 2],     ah0, ah1, ah2, ah3, bh0, bh1);
                mma_f16(acc[np * 2 + 1], ah0, ah1, ah2, ah3, bh2, bh3);
            }
        }
    }

    // partial row sums (every quad holds identical cols; quad leader writes)
    if ((lane & 3) == 0) {
        int r0 = wid * 16 + (lane >> 2);
        g_ps[z * RTOT + base + i0 + r0]     = accRS[0];
        g_ps[z * RTOT + base + i0 + r0 + 8] = accRS[2];
    }

    // partial D store (fp32, no div/relu)
    {
        int r0 = wid * 16 + (lane >> 2);
        int r1 = r0 + 8;
        float* p0 = g_pd + (size_t)z * RTOT * 128 + (size_t)(base + i0 + r0) * FOUT + (lane & 3) * 2;
        float* p1 = g_pd + (size_t)z * RTOT * 128 + (size_t)(base + i0 + r1) * FOUT + (lane & 3) * 2;
#pragma unroll
        for (int n = 0; n < NT; n++) {
            *(float2*)(p0 + n * 8) = make_float2(acc[n][0], acc[n][1]);
            *(float2*)(p1 + n * 8) = make_float2(acc[n][2], acc[n][3]);
        }
    }
}

// ---------------- combine partials: out = relu(sum_z D / sum_z s) ----------
template <int FOUT>
__global__ __launch_bounds__(256) void combine_kernel(float* __restrict__ O) {
    int idx = blockIdx.x * 256 + threadIdx.x;
    int row = idx / (FOUT / 4);
    int c4  = idx % (FOUT / 4);
    float rs = 0.0f;
    float4 d = make_float4(0.f, 0.f, 0.f, 0.f);
#pragma unroll
    for (int zz = 0; zz < ZSPLIT; zz++) {
        rs += g_ps[zz * RTOT + row];
        float4 t = *(const float4*)(g_pd + (size_t)zz * RTOT * 128 + (size_t)row * FOUT + c4 * 4);
        d.x += t.x; d.y += t.y; d.z += t.z; d.w += t.w;
    }
    float inv = 1.0f / rs;
    float4 o;
    o.x = fmaxf(d.x * inv, 0.0f);
    o.y = fmaxf(d.y * inv, 0.0f);
    o.z = fmaxf(d.z * inv, 0.0f);
    o.w = fmaxf(d.w * inv, 0.0f);
    *(float4*)(O + (size_t)row * FOUT + c4 * 4) = o;
}

// ---------------- final linear: y[8,128] = X[8,131072] @ Wlin + blin --------
__global__ __launch_bounds__(128) void final_partial_kernel(
    const float* __restrict__ X, const float* __restrict__ Wlin)
{
    int c  = threadIdx.x;
    int s  = blockIdx.x;
    int k0 = s * 512;
    float acc[8] = {0, 0, 0, 0, 0, 0, 0, 0};
    for (int k = k0; k < k0 + 512; k++) {
        float w = Wlin[(size_t)k * 128 + c];
#pragma unroll
        for (int b = 0; b < 8; b++) acc[b] += X[(size_t)b * 131072 + k] * w;
    }
#pragma unroll
    for (int b = 0; b < 8; b++) g_part[s * 1024 + b * 128 + c] = acc[b];
}

__global__ __launch_bounds__(256) void final_reduce_kernel(
    const float* __restrict__ blin, float* __restrict__ out)
{
    int idx = blockIdx.x * 256 + threadIdx.x;
    if (idx < 1024) {
        float s = 0.0f;
        for (int sp = 0; sp < 256; sp++) s += g_part[sp * 1024 + idx];
        out[idx] = s + blin[idx & 127];
    }
}

// ---------------- host driver ------------------------------------------------
extern "C" void kernel_launch(void* const* d_in, const int* in_sizes, int n_in,
                              void* d_out, int out_size)
{
    const float* x    = (const float*)d_in[0];
    const float* adj  = (const float*)d_in[1];
    const float* W1   = (const float*)d_in[2];
    const float* a1s  = (const float*)d_in[3];
    const float* a1d  = (const float*)d_in[4];
    const float* W2   = (const float*)d_in[5];
    const float* a2s  = (const float*)d_in[6];
    const float* a2d  = (const float*)d_in[7];
    const float* W3   = (const float*)d_in[8];
    const float* a3s  = (const float*)d_in[9];
    const float* a3d  = (const float*)d_in[10];
    const float* Wlin = (const float*)d_in[11];
    const float* blin = (const float*)d_in[12];

    void* phh; cudaGetSymbolAddress(&phh, g_hh);
    void* po;  cudaGetSymbolAddress(&po,  g_o);
    __half* hh = (__half*)phh;
    float* obuf = (float*)po;

    constexpr int SM128 = 22528 + 2 * 128 * 128;  // 55296
    constexpr int SM64  = 22528 + 2 * 64 * 128;   // 38912
    cudaFuncSetAttribute(attn_mma_kernel<128>, cudaFuncAttributeMaxDynamicSharedMemorySize, SM128);
    cudaFuncSetAttribute(attn_mma_kernel<64>,  cudaFuncAttributeMaxDynamicSharedMemorySize, SM64);

    build_mask_kernel<<<16384, 256>>>(adj);

    // layer 1 (128 -> 128)
    sgemm_h_kernel<128><<<256, 256>>>(x, W1, a1s, a1d, hh);
    attn_mma_kernel<128><<<dim3(16, 8, ZSPLIT), 256, SM128>>>(hh);
    combine_kernel<128><<<RTOT * 128 / 4 / 256, 256>>>(obuf);

    // layer 2 (128 -> 128)
    sgemm_h_kernel<128><<<256, 256>>>(obuf, W2, a2s, a2d, hh);
    attn_mma_kernel<128><<<dim3(16, 8, ZSPLIT), 256, SM128>>>(hh);
    combine_kernel<128><<<RTOT * 128 / 4 / 256, 256>>>(obuf);

    // layer 3 (128 -> 64)
    sgemm_h_kernel<64><<<256, 256>>>(obuf, W3, a3s, a3d, hh);
    attn_mma_kernel<64><<<dim3(16, 8, ZSPLIT), 256, SM64>>>(hh);
    combine_kernel<64><<<RTOT * 64 / 4 / 256, 256>>>(obuf);

    // final linear
    final_partial_kernel<<<256, 128>>>(obuf, Wlin);
    final_reduce_kernel<<<4, 256>>>(blin, (float*)d_out);
}

// round 8
// speedup vs baseline: 3.1625x; 1.0095x over previous
#include <cuda_runtime.h>
#include <cuda_fp16.h>
#include <cstdint>

// Problem constants (GATAuto: B=8, N=2048, Fin=128, H=[128,128,64], C=128)
#define BB 8
#define NN 2048
#define RTOT (BB*NN)          // 16384 rows
#define ZSPLIT 4
#define JT_PER ((NN/64)/ZSPLIT)   // 8 j-tiles per z-chunk
#define IGROUPS 4                 // i-groups of 512 rows
#define ITER_I 4                  // 4 x 128-row i-tiles per block

// ---------------- scratch (device globals; no allocation allowed) ----------
__device__ __align__(16) __half g_hh[128 * RTOT];          // h transposed fp16 [o][row]
__device__ __align__(16) float  g_o[RTOT * 128];           // layer outputs (row-major)
__device__ __align__(16) float  g_pd[(size_t)ZSPLIT * RTOT * 128];  // partial D
__device__ float    g_ps[ZSPLIT * RTOT];                   // partial row sums
__device__ float    g_es[RTOT], g_r[RTOT];                 // es, exp(-0.8 es)
__device__ float    g_ed[RTOT], g_v[RTOT], g_q[RTOT];      // ed, exp(ed), exp(0.2 ed)
__device__ unsigned g_mask[NN * (NN / 32)];                // adjacency bitmask, 512KB
__device__ float    g_part[256 * 1024];                    // final-linear split-K partials

// ======================= warp MMA helpers (baseline PTX) =====================
__device__ __forceinline__ uint32_t smem_to_u32(const void* p) {
    uint32_t a;
    asm("{ .reg .u64 t; cvta.to.shared.u64 t, %1; cvt.u32.u64 %0, t; }" : "=r"(a) : "l"(p));
    return a;
}
__device__ __forceinline__ void ldmx4(uint32_t& r0, uint32_t& r1, uint32_t& r2, uint32_t& r3,
                                      uint32_t addr) {
    asm volatile("ldmatrix.sync.aligned.m8n8.x4.shared.b16 {%0,%1,%2,%3}, [%4];"
                 : "=r"(r0), "=r"(r1), "=r"(r2), "=r"(r3) : "r"(addr));
}
__device__ __forceinline__ void mma_f16(float* d, uint32_t a0, uint32_t a1, uint32_t a2,
                                        uint32_t a3, uint32_t b0, uint32_t b1) {
    asm volatile("mma.sync.aligned.m16n8k16.row.col.f32.f16.f16.f32 "
                 "{%0,%1,%2,%3}, {%4,%5,%6,%7}, {%8,%9}, {%0,%1,%2,%3};"
                 : "+f"(d[0]), "+f"(d[1]), "+f"(d[2]), "+f"(d[3])
                 : "r"(a0), "r"(a1), "r"(a2), "r"(a3), "r"(b0), "r"(b1));
}
#define CP_ASYNC16(dst, src) \
    asm volatile("cp.async.ca.shared.global [%0], [%1], 16;" :: "r"(dst), "l"(src))
#define CP_COMMIT() asm volatile("cp.async.commit_group;" ::: "memory")
#define CP_WAIT0()  asm volatile("cp.async.wait_group 0;" ::: "memory")

// fp16x2 packed ops on u32 registers
__device__ __forceinline__ uint32_t hadd2u(uint32_t a, uint32_t b) {
    uint32_t d; asm("add.f16x2 %0, %1, %2;" : "=r"(d) : "r"(a), "r"(b)); return d;
}
__device__ __forceinline__ uint32_t hmul2u(uint32_t a, uint32_t b) {
    uint32_t d; asm("mul.f16x2 %0, %1, %2;" : "=r"(d) : "r"(a), "r"(b)); return d;
}
__device__ __forceinline__ uint32_t hmin2u(uint32_t a, uint32_t b) {
    uint32_t d; asm("min.f16x2 %0, %1, %2;" : "=r"(d) : "r"(a), "r"(b)); return d;
}
__device__ __forceinline__ uint32_t hge2_mask(uint32_t a, uint32_t b) {
    uint32_t d; asm("set.ge.u32.f16x2 %0, %1, %2;" : "=r"(d) : "r"(a), "r"(b)); return d;
}

// ---------------- adjacency bitmask ----------------------------------------
__global__ void build_mask_kernel(const float* __restrict__ adj) {
    int w    = blockIdx.x * 8 + (threadIdx.x >> 5);
    int lane = threadIdx.x & 31;
    int row  = w >> 6;
    int wc   = w & 63;
    float av = adj[(size_t)row * NN + wc * 32 + lane];
    unsigned m = __ballot_sync(0xffffffffu, av > 0.0f);
    if (lane == 0) g_mask[w] = m;
}

// ---------------- h = X @ W, transposed fp16 out + fused stats --------------
template <int FOUT>
__global__ __launch_bounds__(256) void sgemm_h_kernel(
    const float* __restrict__ X, const float* __restrict__ W,
    const float* __restrict__ as, const float* __restrict__ ad,
    __half* __restrict__ Hh)
{
    constexpr int TN = FOUT / 16;
    __shared__ float sX[2][16][68];
    __shared__ float sW[2][16][FOUT + 4];
    __shared__ float sRed1[64][17];
    __shared__ float sRed2[64][17];

    const int tid  = threadIdx.x;
    const int row0 = blockIdx.x * 64;
    const int tr   = tid >> 4;
    const int tc   = tid & 15;

    const int lk = tid & 15;
    const int lr = tid >> 4;

    float xr[4], wr[TN];
    auto ldg_chunk = [&](int f0) {
#pragma unroll
        for (int s = 0; s < 4; s++)
            xr[s] = X[(size_t)(row0 + lr + s * 16) * 128 + f0 + lk];
#pragma unroll
        for (int t = 0; t < TN; t++) {
            int idx = tid + t * 256;
            wr[t] = W[(size_t)(f0 + idx / FOUT) * FOUT + idx % FOUT];
        }
    };
    auto st_chunk = [&](int buf) {
#pragma unroll
        for (int s = 0; s < 4; s++) sX[buf][lk][lr + s * 16] = xr[s];
#pragma unroll
        for (int t = 0; t < TN; t++) {
            int idx = tid + t * 256;
            sW[buf][idx / FOUT][idx % FOUT] = wr[t];
        }
    };

    float acc[4][TN];
#pragma unroll
    for (int r = 0; r < 4; r++)
#pragma unroll
        for (int c = 0; c < TN; c++) acc[r][c] = 0.0f;

    ldg_chunk(0);
    st_chunk(0);
    __syncthreads();

    for (int c8 = 0; c8 < 8; c8++) {
        if (c8 < 7) ldg_chunk((c8 + 1) * 16);
        const int buf = c8 & 1;
#pragma unroll
        for (int k = 0; k < 16; k++) {
            float ra[4], rb[TN];
            *(float4*)ra = *(const float4*)&sX[buf][k][tr * 4];
            if (TN == 8) {
                *(float4*)&rb[0] = *(const float4*)&sW[buf][k][tc * 8];
                *(float4*)&rb[4] = *(const float4*)&sW[buf][k][tc * 8 + 4];
            } else {
                *(float4*)&rb[0] = *(const float4*)&sW[buf][k][tc * 4];
            }
#pragma unroll
            for (int r = 0; r < 4; r++)
#pragma unroll
                for (int c = 0; c < TN; c++) acc[r][c] += ra[r] * rb[c];
        }
        if (c8 < 7) st_chunk(buf ^ 1);
        __syncthreads();
    }

    float s1[4] = {0, 0, 0, 0}, s2[4] = {0, 0, 0, 0};
#pragma unroll
    for (int c = 0; c < TN; c++) {
        float av = __ldg(as + tc * TN + c);
        float dv = __ldg(ad + tc * TN + c);
#pragma unroll
        for (int r = 0; r < 4; r++) {
            s1[r] += acc[r][c] * av;
            s2[r] += acc[r][c] * dv;
        }
    }
#pragma unroll
    for (int r = 0; r < 4; r++) {
        sRed1[tr * 4 + r][tc] = s1[r];
        sRed2[tr * 4 + r][tc] = s2[r];
    }

    // transposed fp16 store
#pragma unroll
    for (int c = 0; c < TN; c++) {
        int col = tc * TN + c;
        __half2 h01 = __float22half2_rn(make_float2(acc[0][c], acc[1][c]));
        __half2 h23 = __float22half2_rn(make_float2(acc[2][c], acc[3][c]));
        size_t off = (size_t)col * RTOT + row0 + tr * 4;
        *(__half2*)(Hh + off)     = h01;
        *(__half2*)(Hh + off + 2) = h23;
    }

    __syncthreads();
    if (tid < 64) {
        float t1 = 0.0f, t2 = 0.0f;
#pragma unroll
        for (int t = 0; t < 16; t++) { t1 += sRed1[tid][t]; t2 += sRed2[tid][t]; }
        int gr = row0 + tid;
        g_es[gr] = t1; g_r[gr] = __expf(-0.8f * t1);
        g_ed[gr] = t2; g_v[gr] = __expf(t2); g_q[gr] = __expf(0.2f * t2);
    }
}

// ---------------- fused masked-attention, B-resident, split-j partials ------
// Block = (i-group of 512 rows) x (z-chunk of 512 j). All 8 B tiles loaded to
// smem ONCE, then 4 i-tiles x 8 j-tiles of barrier-free P-build + MMA.
// Row-normalized P: P'_ij = mask ? ((es_i+ed_j>=0) ? v_j : r_i*q_j) : 0
template <int FOUT, int MINB>
__global__ __launch_bounds__(256, MINB) void attn_mma_kernel(
    const __half* __restrict__ Bh)
{
    constexpr int ROWB = 144;                    // P row stride (bytes)
    constexpr uint32_t OFF_ES  = 0;              // 512 f32
    constexpr uint32_t OFF_R   = 2048;           // 512 f32
    constexpr uint32_t OFF_EDH = 4096;           // 512 half
    constexpr uint32_t OFF_VH  = 5120;           // 512 half
    constexpr uint32_t OFF_QH  = 6144;           // 512 half
    constexpr uint32_t OFF_P   = 7168;           // 128 x 72 f16 (padded rows)
    constexpr uint32_t OFF_B   = OFF_P + 128 * ROWB;     // 25600
    constexpr uint32_t BUFSTRIDE = (uint32_t)FOUT * 128; // per fp16 tile
    constexpr uint32_t ONES  = 0x3C003C00u;      // fp16x2 {1,1}
    constexpr uint32_t CLAMP = 0x7B537B53u;      // fp16x2 {60000,60000}

    extern __shared__ char smem[];
    const uint32_t sb = smem_to_u32(smem);
    const int tid  = threadIdx.x;
    const int wid  = tid >> 5;
    const int lane = tid & 31;

    const int ig   = blockIdx.x;            // i-group (512 rows)
    const int b    = blockIdx.y;
    const int z    = blockIdx.z;
    const int base = b * NN;
    const int irow0 = ig * 512;              // node index of group start
    const int jbase = base + z * (JT_PER * 64);

    float*  ses  = (float*)(smem + OFF_ES);
    float*  sr   = (float*)(smem + OFF_R);
    __half* sedh = (__half*)(smem + OFF_EDH);
    __half* svh  = (__half*)(smem + OFF_VH);
    __half* sqh  = (__half*)(smem + OFF_QH);

    // ---- prologue staging (512 i-rows + 512 j-stats) ----
#pragma unroll
    for (int t = 0; t < 2; t++) {
        int idx = tid + t * 256;
        int i = base + irow0 + idx;
        ses[idx] = g_es[i];
        sr[idx]  = g_r[i];
        sedh[idx] = __float2half(g_ed[jbase + idx]);
        svh[idx]  = __float2half(fminf(g_v[jbase + idx], 60000.0f));
        sqh[idx]  = __float2half(g_q[jbase + idx]);
    }

    // ---- load ALL 8 B tiles once (cp.async, swizzled 128B rows) ----
    {
        constexpr int TOTCH = JT_PER * FOUT * 8;   // 16B chunks
#pragma unroll
        for (int t = 0; t < TOTCH / 256; t++) {
            int idx  = tid + t * 256;
            int tile = idx / (FOUT * 8);
            int rem  = idx % (FOUT * 8);
            int o = rem >> 3, c = rem & 7;
            uint32_t dst = sb + OFF_B + tile * BUFSTRIDE + o * 128
                         + (uint32_t)((c ^ (o & 7)) << 4);
            const char* src = (const char*)(Bh + (size_t)o * RTOT + jbase + tile * 64) + c * 16;
            CP_ASYNC16(dst, src);
        }
    }
    CP_COMMIT();

    // per-thread P-build coordinates (fixed local rows across i-iters)
    const int iP = tid >> 1;
    const int jh = tid & 1;
    char* dstP = smem + OFF_P + iP * ROWB + jh * 64;

    // ldmatrix fixed addresses
    const int arow  = wid * 16 + (lane & 7) + (((lane >> 3) & 1) << 3);
    const int akoff = (lane >> 4) << 4;
    const uint32_t aBase = sb + OFF_P + arow * ROWB + akoff;
    const int brow = (lane & 7) + ((lane >> 4) << 3);
    const int bsel = (lane >> 3) & 1;

    constexpr int NT = FOUT / 8;

    CP_WAIT0();
    __syncthreads();   // B tiles + staging visible; ONLY block barrier

    for (int m = 0; m < ITER_I; m++) {
        const int iloc = m * 128;            // local row offset within group

        // per-thread row constants for this i-tile
        uint32_t es2, ri2;
        {
            __half eh = __float2half(ses[iloc + iP]);
            __half rh = __float2half(fminf(sr[iloc + iP], 60000.0f));
            uint16_t eu = __half_as_ushort(eh), ru = __half_as_ushort(rh);
            es2 = (uint32_t)eu | ((uint32_t)eu << 16);
            ri2 = (uint32_t)ru | ((uint32_t)ru << 16);
        }
        // mask words for this row, all 8 local j-tiles
        unsigned mw[JT_PER];
        {
            const unsigned* mrow = g_mask + (size_t)(irow0 + iloc + iP) * (NN / 32)
                                 + z * (JT_PER * 2) + jh;
#pragma unroll
            for (int l = 0; l < JT_PER; l++) mw[l] = mrow[l * 2];
        }

        float acc[NT][4];
#pragma unroll
        for (int n = 0; n < NT; n++)
#pragma unroll
            for (int q = 0; q < 4; q++) acc[n][q] = 0.0f;
        float accRS[4] = {0.f, 0.f, 0.f, 0.f};

        for (int l = 0; l < JT_PER; l++) {
            // build P rows (warp-local ownership), fp16x2 vectorized
            {
                const unsigned mm0 = mw[l];
                const __half* edl = sedh + l * 64 + (jh << 5);
                const __half* vl  = svh  + l * 64 + (jh << 5);
                const __half* ql  = sqh  + l * 64 + (jh << 5);
#pragma unroll
                for (int jj = 0; jj < 32; jj += 4) {
                    uint2 ed = *(const uint2*)(edl + jj);
                    uint2 vv = *(const uint2*)(vl + jj);
                    uint2 qq = *(const uint2*)(ql + jj);
                    uint32_t t0 = hadd2u(es2, ed.x);
                    uint32_t t1 = hadd2u(es2, ed.y);
                    uint32_t ge0 = hge2_mask(t0, 0u);
                    uint32_t ge1 = hge2_mask(t1, 0u);
                    uint32_t lo0 = hmul2u(ri2, qq.x);
                    uint32_t lo1 = hmul2u(ri2, qq.y);
                    uint32_t a0 = (vv.x & ge0) | (lo0 & ~ge0);
                    uint32_t a1 = (vv.y & ge1) | (lo1 & ~ge1);
                    uint32_t mb = mm0 >> jj;
                    a0 &= ((mb & 1u) * 0xFFFFu) | (((mb >> 1) & 1u) * 0xFFFF0000u);
                    a1 &= (((mb >> 2) & 1u) * 0xFFFFu) | (((mb >> 3) & 1u) * 0xFFFF0000u);
                    a0 = hmin2u(a0, CLAMP);
                    a1 = hmin2u(a1, CLAMP);
                    *(uint2*)(dstP + jj * 2) = make_uint2(a0, a1);
                }
            }
            __syncwarp();

            // MMA from resident B tile l
            const uint32_t bB = sb + OFF_B + l * BUFSTRIDE;
#pragma unroll
            for (int kk = 0; kk < 4; kk++) {
                uint32_t ah0, ah1, ah2, ah3;
                ldmx4(ah0, ah1, ah2, ah3, aBase + kk * 32);
                mma_f16(accRS, ah0, ah1, ah2, ah3, ONES, ONES);
                int cIdx = kk * 2 + bsel;
#pragma unroll
                for (int np = 0; np < NT / 2; np++) {
                    int r = np * 16 + brow;
                    uint32_t ba = bB + r * 128 + (uint32_t)((cIdx ^ (r & 7)) << 4);
                    uint32_t bh0, bh1, bh2, bh3;
                    ldmx4(bh0, bh1, bh2, bh3, ba);
                    mma_f16(acc[np * 2],     ah0, ah1, ah2, ah3, bh0, bh1);
                    mma_f16(acc[np * 2 + 1], ah0, ah1, ah2, ah3, bh2, bh3);
                }
            }
            __syncwarp();   // P reads done before next overwrite (warp-local)
        }

        // partial row sums (quad leader writes)
        if ((lane & 3) == 0) {
            int r0 = wid * 16 + (lane >> 2);
            g_ps[z * RTOT + base + irow0 + iloc + r0]     = accRS[0];
            g_ps[z * RTOT + base + irow0 + iloc + r0 + 8] = accRS[2];
        }

        // partial D store
        {
            int r0 = wid * 16 + (lane >> 2);
            int r1 = r0 + 8;
            size_t rb = (size_t)z * RTOT * 128 + (size_t)(base + irow0 + iloc) * FOUT;
            float* p0 = g_pd + rb + (size_t)r0 * FOUT + (lane & 3) * 2;
            float* p1 = g_pd + rb + (size_t)r1 * FOUT + (lane & 3) * 2;
#pragma unroll
            for (int n = 0; n < NT; n++) {
                *(float2*)(p0 + n * 8) = make_float2(acc[n][0], acc[n][1]);
                *(float2*)(p1 + n * 8) = make_float2(acc[n][2], acc[n][3]);
            }
        }
    }
}

// ---------------- combine partials: out = relu(sum_z D / sum_z s) ----------
template <int FOUT>
__global__ __launch_bounds__(256) void combine_kernel(float* __restrict__ O) {
    int idx = blockIdx.x * 256 + threadIdx.x;
    int row = idx / (FOUT / 4);
    int c4  = idx % (FOUT / 4);
    float rs = 0.0f;
    float4 d = make_float4(0.f, 0.f, 0.f, 0.f);
#pragma unroll
    for (int zz = 0; zz < ZSPLIT; zz++) {
        rs += g_ps[zz * RTOT + row];
        float4 t = *(const float4*)(g_pd + (size_t)zz * RTOT * 128 + (size_t)row * FOUT + c4 * 4);
        d.x += t.x; d.y += t.y; d.z += t.z; d.w += t.w;
    }
    float inv = 1.0f / rs;
    float4 o;
    o.x = fmaxf(d.x * inv, 0.0f);
    o.y = fmaxf(d.y * inv, 0.0f);
    o.z = fmaxf(d.z * inv, 0.0f);
    o.w = fmaxf(d.w * inv, 0.0f);
    *(float4*)(O + (size_t)row * FOUT + c4 * 4) = o;
}

// ---------------- final linear: y[8,128] = X[8,131072] @ Wlin + blin --------
__global__ __launch_bounds__(128) void final_partial_kernel(
    const float* __restrict__ X, const float* __restrict__ Wlin)
{
    int c  = threadIdx.x;
    int s  = blockIdx.x;
    int k0 = s * 512;
    float acc[8] = {0, 0, 0, 0, 0, 0, 0, 0};
    for (int k = k0; k < k0 + 512; k++) {
        float w = Wlin[(size_t)k * 128 + c];
#pragma unroll
        for (int b = 0; b < 8; b++) acc[b] += X[(size_t)b * 131072 + k] * w;
    }
#pragma unroll
    for (int b = 0; b < 8; b++) g_part[s * 1024 + b * 128 + c] = acc[b];
}

__global__ __launch_bounds__(256) void final_reduce_kernel(
    const float* __restrict__ blin, float* __restrict__ out)
{
    int idx = blockIdx.x * 256 + threadIdx.x;
    if (idx < 1024) {
        float s = 0.0f;
        for (int sp = 0; sp < 256; sp++) s += g_part[sp * 1024 + idx];
        out[idx] = s + blin[idx & 127];
    }
}

// ---------------- host driver ------------------------------------------------
extern "C" void kernel_launch(void* const* d_in, const int* in_sizes, int n_in,
                              void* d_out, int out_size)
{
    const float* x    = (const float*)d_in[0];
    const float* adj  = (const float*)d_in[1];
    const float* W1   = (const float*)d_in[2];
    const float* a1s  = (const float*)d_in[3];
    const float* a1d  = (const float*)d_in[4];
    const float* W2   = (const float*)d_in[5];
    const float* a2s  = (const float*)d_in[6];
    const float* a2d  = (const float*)d_in[7];
    const float* W3   = (const float*)d_in[8];
    const float* a3s  = (const float*)d_in[9];
    const float* a3d  = (const float*)d_in[10];
    const float* Wlin = (const float*)d_in[11];
    const float* blin = (const float*)d_in[12];

    void* phh; cudaGetSymbolAddress(&phh, g_hh);
    void* po;  cudaGetSymbolAddress(&po,  g_o);
    __half* hh = (__half*)phh;
    float* obuf = (float*)po;

    constexpr int SM128 = 25600 + 8 * 128 * 128;  // 156672
    constexpr int SM64  = 25600 + 8 * 64 * 128;   // 91136
    cudaFuncSetAttribute(attn_mma_kernel<128, 1>, cudaFuncAttributeMaxDynamicSharedMemorySize, SM128);
    cudaFuncSetAttribute(attn_mma_kernel<64, 2>,  cudaFuncAttributeMaxDynamicSharedMemorySize, SM64);

    build_mask_kernel<<<16384, 256>>>(adj);

    // layer 1 (128 -> 128)
    sgemm_h_kernel<128><<<256, 256>>>(x, W1, a1s, a1d, hh);
    attn_mma_kernel<128, 1><<<dim3(IGROUPS, 8, ZSPLIT), 256, SM128>>>(hh);
    combine_kernel<128><<<RTOT * 128 / 4 / 256, 256>>>(obuf);

    // layer 2 (128 -> 128)
    sgemm_h_kernel<128><<<256, 256>>>(obuf, W2, a2s, a2d, hh);
    attn_mma_kernel<128, 1><<<dim3(IGROUPS, 8, ZSPLIT), 256, SM128>>>(hh);
    combine_kernel<128><<<RTOT * 128 / 4 / 256, 256>>>(obuf);

    // layer 3 (128 -> 64)
    sgemm_h_kernel<64><<<256, 256>>>(obuf, W3, a3s, a3d, hh);
    attn_mma_kernel<64, 2><<<dim3(IGROUPS, 8, ZSPLIT), 256, SM64>>>(hh);
    combine_kernel<64><<<RTOT * 64 / 4 / 256, 256>>>(obuf);

    // final linear
    final_partial_kernel<<<256, 128>>>(obuf, Wlin);
    final_reduce_kernel<<<4, 256>>>(blin, (float*)d_out);
}